// round 11
// baseline (speedup 1.0000x reference)
#include <cuda_runtime.h>
#include <cuda_bf16.h>
#include <math.h>
#include <stdint.h>

#define MR 32768
#define LSEQ 4096
#define NBATCH 8
#define NLAYER 3
#define NCHK 32
#define CLEN 128

typedef __nv_bfloat16 bf16;

// ---------------- scratch ----------------
__device__ __align__(256) float g_h  [(size_t)MR * 512];
__device__ __align__(256) float g_b2 [(size_t)MR * 512];
__device__ __align__(256) float g_big[(size_t)MR * 1024];
__device__ __align__(256) bf16 g_b1h[(size_t)MR * 512];
__device__ __align__(256) bf16 g_b1l[(size_t)MR * 512];
__device__ __align__(256) bf16 g_xh [(size_t)MR * 1024];
__device__ __align__(256) bf16 g_xl [(size_t)MR * 1024];
__device__ __align__(256) bf16 g_xbh[(size_t)MR * 64];
__device__ __align__(256) bf16 g_xbl[(size_t)MR * 64];
__device__ __align__(256) bf16 g_wbh[1024 * 512];
__device__ __align__(256) bf16 g_wbl[1024 * 512];
__device__ __align__(256) bf16 g_wch[512 * 1024];
__device__ __align__(256) bf16 g_wcl[512 * 1024];
__device__ __align__(256) bf16 g_feh[1024 * 512];
__device__ __align__(256) bf16 g_fel[1024 * 512];
__device__ __align__(256) bf16 g_fdh[512 * 512];
__device__ __align__(256) bf16 g_fdl[512 * 512];
__device__ __align__(256) bf16 g_weh[512 * 64];
__device__ __align__(256) bf16 g_wel[512 * 64];
__device__ __align__(256) float2 g_lb[512];
__device__ __align__(256) float2 g_lbN[512];
__device__ __align__(256) float2 g_carry[NBATCH * NCHK * 512];
__device__ __align__(256) float g_pool[NBATCH * NCHK * 512];

__device__ __forceinline__ float geluf(float x) {
    return 0.5f * x * (1.0f + erff(x * 0.70710678118654752f));
}
__device__ __forceinline__ uint32_t s2u(const void* p) {
    uint32_t a;
    asm("{ .reg .u64 t; cvta.to.shared.u64 t, %1; cvt.u32.u64 %0, t; }" : "=r"(a) : "l"(p));
    return a;
}
__device__ __forceinline__ void split1(float v, bf16* oh, bf16* ol) {
    bf16 h = __float2bfloat16(v);
    *oh = h;
    *ol = __float2bfloat16(v - __bfloat162float(h));
}
__device__ __forceinline__ uint32_t pack2(bf16 a, bf16 b) {
    union { bf16 h[2]; uint32_t u; } u;
    u.h[0] = a; u.h[1] = b;
    return u.u;
}
__device__ __forceinline__ void split4(float4 y, bf16* oh, bf16* ol) {
    union { bf16 b[4]; uint2 u; } H, L;
    float f[4] = {y.x, y.y, y.z, y.w};
#pragma unroll
    for (int e = 0; e < 4; e++) {
        bf16 h = __float2bfloat16(f[e]);
        H.b[e] = h;
        L.b[e] = __float2bfloat16(f[e] - __bfloat162float(h));
    }
    *(uint2*)oh = H.u;
    *(uint2*)ol = L.u;
}
__device__ __forceinline__ float2 rec2(const bf16* ph, const bf16* pl) {
    __nv_bfloat162 hh = *(const __nv_bfloat162*)ph;
    __nv_bfloat162 ll = *(const __nv_bfloat162*)pl;
    return make_float2(__bfloat162float(hh.x) + __bfloat162float(ll.x),
                       __bfloat162float(hh.y) + __bfloat162float(ll.y));
}
__device__ __forceinline__ float2 cmul(float2 a, float2 b) {
    return make_float2(a.x * b.x - a.y * b.y, a.x * b.y + a.y * b.x);
}

#define LDSM4(r0, r1, r2, r3, a) \
    asm volatile("ldmatrix.sync.aligned.m8n8.x4.shared.b16 {%0,%1,%2,%3}, [%4];" \
                 : "=r"(r0), "=r"(r1), "=r"(r2), "=r"(r3) : "r"(a))

#define MMA16816(c, a0, a1, a2, a3, b0, b1) \
    asm volatile("mma.sync.aligned.m16n8k16.row.col.f32.bf16.bf16.f32 " \
                 "{%0,%1,%2,%3}, {%4,%5,%6,%7}, {%8,%9}, {%0,%1,%2,%3};" \
                 : "+f"((c)[0]), "+f"((c)[1]), "+f"((c)[2]), "+f"((c)[3]) \
                 : "r"(a0), "r"(a1), "r"(a2), "r"(a3), "r"(b0), "r"(b1))

// ---------------- HMMA GEMM: 128x128 block, BK=32, 3-stage swizzled, 2 blocks/SM ---
#define MATB 8192
#define STG (4 * MATB)
#define GSMEM (3 * STG)
#define SCARRY_OFF 65536

__device__ __forceinline__ uint32_t swadr(uint32_t row, uint32_t c16) {
    return row * 64 + ((c16 ^ ((row >> 1) & 3)) << 4);
}

template <int EPI>
__global__ void __launch_bounds__(256, 2)
gemm_tc(const bf16* __restrict__ Ah, const bf16* __restrict__ Al, int lda,
        const bf16* __restrict__ Wh, const bf16* __restrict__ Wl, int K,
        float* __restrict__ C, int ldc,
        const float* __restrict__ vec,
        const bf16* __restrict__ math, const bf16* __restrict__ matl,
        bf16* __restrict__ oh, bf16* __restrict__ ol)
{
    extern __shared__ char smembuf[];
    const uint32_t sb = s2u(smembuf);
    const int tid = threadIdx.x, lane = tid & 31, wid = tid >> 5;
    const int warpM = wid & 3, warpN = wid >> 2;
    const int bm = blockIdx.y << 7, bn = blockIdx.x << 7;
    const int NCH = K >> 5;

    float c[2][8][4];
#pragma unroll
    for (int i = 0; i < 2; i++)
#pragma unroll
        for (int j = 0; j < 8; j++)
#pragma unroll
            for (int q = 0; q < 4; q++) c[i][j][q] = 0.f;

    auto LOAD = [&](int ch) {
        if (ch < NCH) {
            uint32_t base = sb + (ch % 3) * STG;
            const bf16* gp[4] = {
                Ah + (size_t)bm * lda + ch * 32,
                Al + (size_t)bm * lda + ch * 32,
                Wh + (size_t)bn * K + ch * 32,
                Wl + (size_t)bn * K + ch * 32 };
            const int ld4[4] = {lda, lda, K, K};
#pragma unroll
            for (int mt = 0; mt < 4; mt++) {
                uint32_t mb = base + mt * MATB;
                const bf16* g = gp[mt];
                int ld = ld4[mt];
#pragma unroll
                for (int q = 0; q < 2; q++) {
                    int idx = tid + q * 256;
                    uint32_t row = idx >> 2, c16 = idx & 3;
                    uint32_t d = mb + swadr(row, c16);
                    const bf16* src = g + (size_t)row * ld + c16 * 8;
                    asm volatile("cp.async.cg.shared.global [%0], [%1], 16;"
                                 :: "r"(d), "l"(src) : "memory");
                }
            }
        }
        asm volatile("cp.async.commit_group;" ::: "memory");
    };

    LOAD(0); LOAD(1);

    for (int ch = 0; ch < NCH; ch++) {
        asm volatile("cp.async.wait_group 1;" ::: "memory");
        __syncthreads();
        LOAD(ch + 2);

        uint32_t base = sb + (ch % 3) * STG;
#pragma unroll
        for (int kk = 0; kk < 2; kk++) {
            uint32_t c16 = kk * 2 + (lane >> 4);
            uint32_t ah[2][4], al[2][4];
#pragma unroll
            for (int mf = 0; mf < 2; mf++) {
                uint32_t row = warpM * 32 + mf * 16 + (lane & 15);
                uint32_t a0 = base + swadr(row, c16);
                LDSM4(ah[mf][0], ah[mf][1], ah[mf][2], ah[mf][3], a0);
                LDSM4(al[mf][0], al[mf][1], al[mf][2], al[mf][3], a0 + MATB);
            }
#pragma unroll
            for (int g = 0; g < 4; g++) {
                uint32_t row = warpN * 64 + g * 16 + (lane & 15);
                uint32_t a0 = base + 2 * MATB + swadr(row, c16);
                uint32_t h0, h1, h2, h3, l0, l1, l2, l3;
                LDSM4(h0, h1, h2, h3, a0);
                LDSM4(l0, l1, l2, l3, a0 + MATB);
#pragma unroll
                for (int mf = 0; mf < 2; mf++) {
                    MMA16816(c[mf][2*g],   ah[mf][0], ah[mf][1], ah[mf][2], ah[mf][3], h0, h2);
                    MMA16816(c[mf][2*g+1], ah[mf][0], ah[mf][1], ah[mf][2], ah[mf][3], h1, h3);
                }
#pragma unroll
                for (int mf = 0; mf < 2; mf++) {
                    MMA16816(c[mf][2*g],   ah[mf][0], ah[mf][1], ah[mf][2], ah[mf][3], l0, l2);
                    MMA16816(c[mf][2*g+1], ah[mf][0], ah[mf][1], ah[mf][2], ah[mf][3], l1, l3);
                }
#pragma unroll
                for (int mf = 0; mf < 2; mf++) {
                    MMA16816(c[mf][2*g],   al[mf][0], al[mf][1], al[mf][2], al[mf][3], h0, h2);
                    MMA16816(c[mf][2*g+1], al[mf][0], al[mf][1], al[mf][2], al[mf][3], h1, h3);
                }
            }
        }
    }

    if (EPI == 5) {
        // parallel segmented scan: 64 complex chains x 4 segments of 32 steps
        float* sc = (float*)smembuf;
        float2* scar = (float2*)(smembuf + SCARRY_OFF);   // [4][64]
        __syncthreads();
#pragma unroll
        for (int mf = 0; mf < 2; mf++) {
            int r0 = warpM * 32 + mf * 16 + (lane >> 2);
#pragma unroll
            for (int jb = 0; jb < 8; jb++) {
                int n = warpN * 64 + jb * 8 + 2 * (lane & 3);
#pragma unroll
                for (int half = 0; half < 2; half++) {
                    *(float2*)&sc[(r0 + half * 8) * 128 + n] =
                        make_float2(c[mf][jb][2 * half], c[mf][jb][2 * half + 1]);
                }
            }
        }
        __syncthreads();
        {
            int j = tid & 63, seg = tid >> 6;
            int t0 = seg * 32;
            int pglob = (bn >> 1) + j;
            float2 lb = g_lb[pglob];
            // pass 1: zero-seed local scan, in place
            float xr = 0.f, xi = 0.f;
#pragma unroll 4
            for (int t = 0; t < 32; t++) {
                float2* pp = (float2*)&sc[(t0 + t) * 128 + 2 * j];
                float2 bu = *pp;
                float nr = fmaf(lb.x, xr, fmaf(-lb.y, xi, bu.x));
                float ni = fmaf(lb.x, xi, fmaf(lb.y, xr, bu.y));
                xr = nr; xi = ni;
                *pp = make_float2(xr, xi);
            }
            scar[seg * 64 + j] = make_float2(xr, xi);
            __syncthreads();
            // seed = sum_{k<seg} lb32^(seg-k) * carry_k
            float2 pw32 = lb;
#pragma unroll
            for (int q = 0; q < 5; q++) pw32 = cmul(pw32, pw32);   // lb^32
            float2 s = make_float2(0.f, 0.f);
            for (int k = 0; k < seg; k++) {
                float2 ck = scar[k * 64 + j];
                float nr = fmaf(pw32.x, s.x, fmaf(-pw32.y, s.y, ck.x));
                float ni = fmaf(pw32.x, s.y, fmaf(pw32.y, s.x, ck.y));
                s = make_float2(nr, ni);
            }
            // pass 2: x_t = local_t + lb^(t+1) * s ; write to gmem
            float* outp = g_big + (size_t)(bm + t0) * 1024 + bn + 2 * j;
            float2 pw = lb;
            float2 last = make_float2(0.f, 0.f);
#pragma unroll 4
            for (int t = 0; t < 32; t++) {
                float2 l = *(float2*)&sc[(t0 + t) * 128 + 2 * j];
                float2 v = make_float2(fmaf(pw.x, s.x, fmaf(-pw.y, s.y, l.x)),
                                       fmaf(pw.x, s.y, fmaf(pw.y, s.x, l.y)));
                *(float2*)(outp + (size_t)t * 1024) = v;
                pw = cmul(pw, lb);
                last = v;
            }
            if (seg == 3) {
                int b = bm >> 12, cch = (bm >> 7) & 31;
                g_carry[((size_t)b * NCHK + cch) * 512 + pglob] = last;
            }
        }
        return;
    }

#pragma unroll
    for (int mf = 0; mf < 2; mf++) {
        int m0 = bm + warpM * 32 + mf * 16 + (lane >> 2);
#pragma unroll
        for (int jb = 0; jb < 8; jb++) {
            int n = bn + warpN * 64 + jb * 8 + 2 * (lane & 3);
#pragma unroll
            for (int half = 0; half < 2; half++) {
                int r = m0 + half * 8;
                float v0 = c[mf][jb][2 * half], v1 = c[mf][jb][2 * half + 1];
                if (EPI == 4) {
                    int j = ((bn + warpN * 64 + jb * 8) >> 1) + (lane & 3);
                    size_t off = (size_t)r * 512 + j;
                    split1(v0 * geluf(v1), oh + off, ol + off);
                } else {
                    size_t off = (size_t)r * ldc + n;
                    if (EPI == 1) {
                        float2 bv = *(const float2*)(vec + n);
                        v0 += bv.x; v1 += bv.y;
                    } else if (EPI == 2) {
                        float2 u = rec2(math + (size_t)r * 512 + n, matl + (size_t)r * 512 + n);
                        float2 dv = *(const float2*)(vec + n);
                        v0 = geluf(v0 + dv.x * u.x) + u.x;
                        v1 = geluf(v1 + dv.y * u.y) + u.y;
                    } else if (EPI == 3) {
                        float2 u = rec2(math + (size_t)r * 512 + n, matl + (size_t)r * 512 + n);
                        float2 co = *(const float2*)(C + off);
                        v0 += co.x + u.x; v1 += co.y + u.y;
                    }
                    *(float2*)(C + off) = make_float2(v0, v1);
                }
            }
        }
    }
}

// ---------------- LayerNorm (warp per row) ----------------
__device__ __forceinline__ float wsum(float x) {
#pragma unroll
    for (int o = 16; o; o >>= 1) x += __shfl_xor_sync(0xFFFFFFFFu, x, o);
    return x;
}
__device__ __forceinline__ void ln_stage(float4 v[4], const float* __restrict__ w,
                                         const float* __restrict__ b, int l) {
    float s = 0.f;
#pragma unroll
    for (int q = 0; q < 4; q++) s += v[q].x + v[q].y + v[q].z + v[q].w;
    float mean = wsum(s) * (1.f / 512.f);
    float vv = 0.f;
#pragma unroll
    for (int q = 0; q < 4; q++) {
        v[q].x -= mean; v[q].y -= mean; v[q].z -= mean; v[q].w -= mean;
        vv += v[q].x * v[q].x + v[q].y * v[q].y + v[q].z * v[q].z + v[q].w * v[q].w;
    }
    float rs = rsqrtf(wsum(vv) * (1.f / 512.f) + 1e-5f);
#pragma unroll
    for (int q = 0; q < 4; q++) {
        int cc = (l + q * 32) * 4;
        float4 wf = *(const float4*)(w + cc);
        float4 bf = *(const float4*)(b + cc);
        v[q].x = v[q].x * rs * wf.x + bf.x;
        v[q].y = v[q].y * rs * wf.y + bf.y;
        v[q].z = v[q].z * rs * wf.z + bf.z;
        v[q].w = v[q].w * rs * wf.w + bf.w;
    }
}

template <int TWO>
__global__ void __launch_bounds__(256)
ln_kernel(const float* __restrict__ in,
          bf16* __restrict__ oh, bf16* __restrict__ ol,
          const float* __restrict__ w1, const float* __restrict__ b1,
          const float* __restrict__ w2, const float* __restrict__ b2)
{
    int row = blockIdx.x * 8 + (threadIdx.x >> 5);
    int l = threadIdx.x & 31;
    const float4* xr = (const float4*)(in + (size_t)row * 512);
    float4 v[4];
#pragma unroll
    for (int q = 0; q < 4; q++) v[q] = xr[l + q * 32];
    ln_stage(v, w1, b1, l);
    if (TWO) ln_stage(v, w2, b2, l);
#pragma unroll
    for (int q = 0; q < 4; q++) {
        size_t off = (size_t)row * 512 + (size_t)(l + q * 32) * 4;
        split4(v[q], oh + off, ol + off);
    }
}

// ---------------- per-layer prep ----------------
__device__ __forceinline__ float2 coef_of(float lr, float li, float lstep,
                                          float* lbx, float* lby)
{
    float st = expf(lstep);
    float er = expf(lr * st);
    float cc = er * cosf(li * st);
    float ss = er * sinf(li * st);
    *lbx = cc; *lby = ss;
    float den = lr * lr + li * li;
    return make_float2(((cc - 1.f) * lr + ss * li) / den, (ss * lr - (cc - 1.f) * li) / den);
}

__device__ __forceinline__ void prep_layer_body(int blk, int tid,
                           const float* __restrict__ lam_re, const float* __restrict__ lam_im,
                           const float* __restrict__ log_step,
                           const float* __restrict__ Bre, const float* __restrict__ Bim,
                           const float* __restrict__ Cre, const float* __restrict__ Cim,
                           const float* __restrict__ ffe, const float* __restrict__ ffd)
{
    if (blk < 1024) {
        int idx = blk * 256 + tid;
        int p = idx >> 9, d = idx & 511;
        float lbx, lby;
        float2 cf = coef_of(lam_re[p], lam_im[p], log_step[p], &lbx, &lby);
        float br = Bre[idx], bi = Bim[idx];
        split1(cf.x * br - cf.y * bi, &g_wbh[(size_t)(2 * p) * 512 + d], &g_wbl[(size_t)(2 * p) * 512 + d]);
        split1(cf.x * bi + cf.y * br, &g_wbh[(size_t)(2 * p + 1) * 512 + d], &g_wbl[(size_t)(2 * p + 1) * 512 + d]);
    } else if (blk < 2048) {
        int idx = (blk - 1024) * 256 + tid;
        int d = idx >> 9, p = idx & 511;
        split1(2.f * Cre[idx], &g_wch[(size_t)d * 1024 + 2 * p], &g_wcl[(size_t)d * 1024 + 2 * p]);
        split1(-2.f * Cim[idx], &g_wch[(size_t)d * 1024 + 2 * p + 1], &g_wcl[(size_t)d * 1024 + 2 * p + 1]);
    } else if (blk < 4096) {
        int idx = (blk - 2048) * 256 + tid;
        int r = idx >> 9, k = idx & 511;
        int src = (r & 1) ? (512 + (r >> 1)) : (r >> 1);
        split1(ffe[(size_t)src * 512 + k], &g_feh[(size_t)r * 512 + k], &g_fel[(size_t)r * 512 + k]);
    } else if (blk < 5120) {
        int idx = (blk - 4096) * 256 + tid;
        split1(ffd[idx], &g_fdh[idx], &g_fdl[idx]);
    } else {
        int p = (blk - 5120) * 256 + tid;
        float lbx, lby;
        coef_of(lam_re[p], lam_im[p], log_step[p], &lbx, &lby);
        g_lb[p] = make_float2(lbx, lby);
        float ar = lbx, ai = lby;
#pragma unroll
        for (int i = 0; i < 7; i++) {
            float nr = ar * ar - ai * ai, ni = 2.f * ar * ai;
            ar = nr; ai = ni;
        }
        g_lbN[p] = make_float2(ar, ai);
    }
}

__global__ void prep_layer(const float* __restrict__ lam_re, const float* __restrict__ lam_im,
                           const float* __restrict__ log_step,
                           const float* __restrict__ Bre, const float* __restrict__ Bim,
                           const float* __restrict__ Cre, const float* __restrict__ Cim,
                           const float* __restrict__ ffe, const float* __restrict__ ffd)
{
    prep_layer_body(blockIdx.x, threadIdx.x, lam_re, lam_im, log_step,
                    Bre, Bim, Cre, Cim, ffe, ffd);
}

__global__ void prep_all(const float* __restrict__ x, const float* __restrict__ enc_w,
                         const float* __restrict__ lam_re, const float* __restrict__ lam_im,
                         const float* __restrict__ log_step,
                         const float* __restrict__ Bre, const float* __restrict__ Bim,
                         const float* __restrict__ Cre, const float* __restrict__ Cim,
                         const float* __restrict__ ffe, const float* __restrict__ ffd)
{
    int blk = blockIdx.x, tid = threadIdx.x;
    if (blk < 2048) {
        int idx = blk * 256 + tid;
        int mrow = idx >> 4, q = idx & 15;
        float4 v = *(const float4*)(x + (size_t)mrow * 64 + q * 4);
        size_t off = (size_t)mrow * 64 + (size_t)q * 4;
        split4(v, g_xbh + off, g_xbl + off);
    } else if (blk < 2176) {
        int idx = (blk - 2048) * 256 + tid;
        int k = idx >> 9, n = idx & 511;
        split1(enc_w[idx], &g_weh[(size_t)n * 64 + k], &g_wel[(size_t)n * 64 + k]);
    } else {
        prep_layer_body(blk - 2176, tid, lam_re, lam_im, log_step,
                        Bre, Bim, Cre, Cim, ffe, ffd);
    }
}

// ---------------- scan pass3 (carry combine folded in) ----------------
__global__ void scan_pass3()
{
    const int p = threadIdx.x;
    const int c = blockIdx.x, b = blockIdx.y;
    float2 lb = g_lb[p];
    float2 A = g_lbN[p];
    // seed = inclusive combine of raw chunk carries k < c
    float2 cv = make_float2(0.f, 0.f);
    for (int k = 0; k < c; k++) {
        float2 ck = g_carry[((size_t)b * NCHK + k) * 512 + p];
        float nr = fmaf(A.x, cv.x, fmaf(-A.y, cv.y, ck.x));
        float ni = fmaf(A.x, cv.y, fmaf(A.y, cv.x, ck.y));
        cv = make_float2(nr, ni);
    }
    float pr = lb.x, pi = lb.y;
    size_t row0 = (size_t)(b * LSEQ + c * CLEN);
    const float2* loc = (const float2*)(g_big + row0 * 1024) + p;
    uint32_t* xh = (uint32_t*)(g_xh + row0 * 1024) + p;
    uint32_t* xl = (uint32_t*)(g_xl + row0 * 1024) + p;
    for (int t = 0; t < CLEN; t++) {
        float2 l = loc[(size_t)t * 512];
        float xr = fmaf(pr, cv.x, fmaf(-pi, cv.y, l.x));
        float xi = fmaf(pr, cv.y, fmaf(pi, cv.x, l.y));
        float nr = pr * lb.x - pi * lb.y;
        pi = pr * lb.y + pi * lb.x; pr = nr;
        bf16 hr = __float2bfloat16(xr);
        bf16 hi2 = __float2bfloat16(xi);
        xh[(size_t)t * 512] = pack2(hr, hi2);
        xl[(size_t)t * 512] = pack2(__float2bfloat16(xr - __bfloat162float(hr)),
                                    __float2bfloat16(xi - __bfloat162float(hi2)));
    }
}

// ---------------- pool (2-stage) + head ----------------
__global__ void pool_partial(const int* __restrict__ lengths)
{
    const int b = blockIdx.x, c = blockIdx.y;
    const int d = threadIdx.x;
    int len = lengths[b];
    int t0 = c * CLEN;
    int t1 = t0 + CLEN < len ? t0 + CLEN : len;
    float s = 0.f;
    const float* hp = g_h + ((size_t)(b * LSEQ + t0)) * 512 + d;
    for (int t = t0; t < t1; t++) { s += hp[0]; hp += 512; }
    g_pool[((size_t)b * NCHK + c) * 512 + d] = s;
}

__global__ void pool_head(const int* __restrict__ lengths,
                          const float* __restrict__ hw, const float* __restrict__ hb,
                          float* __restrict__ out)
{
    const int b = blockIdx.x;
    const int d = threadIdx.x;
    float s = 0.f;
#pragma unroll
    for (int c = 0; c < NCHK; c++) s += g_pool[((size_t)b * NCHK + c) * 512 + d];
    int len = lengths[b];
    int den = len > 1 ? len : 1;
    float v = (s / (float)den) * hw[d];
    __shared__ float red[512];
    red[d] = v; __syncthreads();
    for (int st = 256; st > 0; st >>= 1) { if (d < st) red[d] += red[d + st]; __syncthreads(); }
    if (d == 0) out[b] = red[0] + hb[0];
}

// ---------------- launch ----------------
extern "C" void kernel_launch(void* const* d_in, const int* in_sizes, int n_in,
                              void* d_out, int out_size)
{
    const float* x       = (const float*)d_in[0];
    const int*   lengths = (const int*)  d_in[1];
    const float* enc_w   = (const float*)d_in[2];
    const float* enc_b   = (const float*)d_in[3];
    const float* lam_re  = (const float*)d_in[4];
    const float* lam_im  = (const float*)d_in[5];
    const float* Bre     = (const float*)d_in[6];
    const float* Bim     = (const float*)d_in[7];
    const float* Cre     = (const float*)d_in[8];
    const float* Cim     = (const float*)d_in[9];
    const float* Dp      = (const float*)d_in[10];
    const float* log_step= (const float*)d_in[11];
    const float* an_w    = (const float*)d_in[12];
    const float* an_b    = (const float*)d_in[13];
    const float* fn_w    = (const float*)d_in[14];
    const float* fn_b    = (const float*)d_in[15];
    const float* ffe_w   = (const float*)d_in[16];
    const float* ffd_w   = (const float*)d_in[17];
    const float* norm_w  = (const float*)d_in[18];
    const float* norm_b  = (const float*)d_in[19];
    const float* head_w  = (const float*)d_in[20];
    const float* head_b  = (const float*)d_in[21];
    float* out = (float*)d_out;

    cudaFuncSetAttribute(gemm_tc<1>, cudaFuncAttributeMaxDynamicSharedMemorySize, GSMEM);
    cudaFuncSetAttribute(gemm_tc<2>, cudaFuncAttributeMaxDynamicSharedMemorySize, GSMEM);
    cudaFuncSetAttribute(gemm_tc<3>, cudaFuncAttributeMaxDynamicSharedMemorySize, GSMEM);
    cudaFuncSetAttribute(gemm_tc<4>, cudaFuncAttributeMaxDynamicSharedMemorySize, GSMEM);
    cudaFuncSetAttribute(gemm_tc<5>, cudaFuncAttributeMaxDynamicSharedMemorySize, GSMEM);

    void *p_h, *p_b2, *p_big, *p_b1h, *p_b1l, *p_xh, *p_xl, *p_xbh, *p_xbl;
    void *p_wbh, *p_wbl, *p_wch, *p_wcl, *p_feh, *p_fel, *p_fdh, *p_fdl, *p_weh, *p_wel;
    cudaGetSymbolAddress(&p_h, g_h);
    cudaGetSymbolAddress(&p_b2, g_b2);   cudaGetSymbolAddress(&p_big, g_big);
    cudaGetSymbolAddress(&p_b1h, g_b1h); cudaGetSymbolAddress(&p_b1l, g_b1l);
    cudaGetSymbolAddress(&p_xh, g_xh);   cudaGetSymbolAddress(&p_xl, g_xl);
    cudaGetSymbolAddress(&p_xbh, g_xbh); cudaGetSymbolAddress(&p_xbl, g_xbl);
    cudaGetSymbolAddress(&p_wbh, g_wbh); cudaGetSymbolAddress(&p_wbl, g_wbl);
    cudaGetSymbolAddress(&p_wch, g_wch); cudaGetSymbolAddress(&p_wcl, g_wcl);
    cudaGetSymbolAddress(&p_feh, g_feh); cudaGetSymbolAddress(&p_fel, g_fel);
    cudaGetSymbolAddress(&p_fdh, g_fdh); cudaGetSymbolAddress(&p_fdl, g_fdl);
    cudaGetSymbolAddress(&p_weh, g_weh); cudaGetSymbolAddress(&p_wel, g_wel);
    float* h   = (float*)p_h;
    float* b2  = (float*)p_b2; float* big = (float*)p_big;
    bf16* b1h = (bf16*)p_b1h; bf16* b1l = (bf16*)p_b1l;
    bf16* xh  = (bf16*)p_xh;  bf16* xl  = (bf16*)p_xl;
    bf16* xbh = (bf16*)p_xbh; bf16* xbl = (bf16*)p_xbl;
    bf16* wbh = (bf16*)p_wbh; bf16* wbl = (bf16*)p_wbl;
    bf16* wch = (bf16*)p_wch; bf16* wcl = (bf16*)p_wcl;
    bf16* feh = (bf16*)p_feh; bf16* fel = (bf16*)p_fel;
    bf16* fdh = (bf16*)p_fdh; bf16* fdl = (bf16*)p_fdl;
    bf16* weh = (bf16*)p_weh; bf16* wel = (bf16*)p_wel;

    prep_all<<<7298, 256>>>(x, enc_w, lam_re, lam_im, log_step,
                            Bre, Bim, Cre, Cim, ffe_w, ffd_w);
    gemm_tc<1><<<dim3(4, 256), 256, GSMEM>>>(xbh, xbl, 64, weh, wel, 64,
                                             h, 512, enc_b, nullptr, nullptr, nullptr, nullptr);

    for (int i = 0; i < NLAYER; i++) {
        if (i > 0)
            prep_layer<<<5122, 256>>>(lam_re + i * 512, lam_im + i * 512, log_step + i * 512,
                                      Bre + (size_t)i * 512 * 512, Bim + (size_t)i * 512 * 512,
                                      Cre + (size_t)i * 512 * 512, Cim + (size_t)i * 512 * 512,
                                      ffe_w + (size_t)i * 1024 * 512, ffd_w + (size_t)i * 512 * 512);
        ln_kernel<1><<<MR / 8, 256>>>(h, b1h, b1l,
                                      norm_w + i * 512, norm_b + i * 512,
                                      an_w + i * 512, an_b + i * 512);
        // launch #4 (i=0): Bu GEMM + fused parallel chunk scan  <- ncu capture target
        gemm_tc<5><<<dim3(8, 256), 256, GSMEM>>>(b1h, b1l, 512, wbh, wbl, 512,
                                                 big, 1024, nullptr, nullptr, nullptr, nullptr, nullptr);
        scan_pass3<<<dim3(NCHK, NBATCH), 512>>>();
        gemm_tc<2><<<dim3(4, 256), 256, GSMEM>>>(xh, xl, 1024, wch, wcl, 1024,
                                                 b2, 512, Dp + i * 512, b1h, b1l, nullptr, nullptr);
        ln_kernel<0><<<MR / 8, 256>>>(b2, b1h, b1l, fn_w + i * 512, fn_b + i * 512,
                                      nullptr, nullptr);
        gemm_tc<4><<<dim3(8, 256), 256, GSMEM>>>(b1h, b1l, 512, feh, fel, 512,
                                                 nullptr, 512, nullptr, nullptr, nullptr, xh, xl);
        gemm_tc<3><<<dim3(4, 256), 256, GSMEM>>>(xh, xl, 512, fdh, fdl, 512,
                                                 h, 512, nullptr, b1h, b1l, nullptr, nullptr);
    }

    pool_partial<<<dim3(NBATCH, NCHK), 512>>>(lengths);
    pool_head<<<NBATCH, 512>>>(lengths, head_w, head_b, out);
}

// round 12
// speedup vs baseline: 1.3433x; 1.3433x over previous
#include <cuda_runtime.h>
#include <cuda_fp16.h>
#include <math.h>
#include <stdint.h>

#define MR 32768
#define LSEQ 4096
#define NBATCH 8
#define NLAYER 3
#define NCHK 32
#define CLEN 128

typedef __half hf;

// ---------------- scratch ----------------
__device__ __align__(256) float g_h  [(size_t)MR * 512];
__device__ __align__(256) float g_b2 [(size_t)MR * 512];
__device__ __align__(256) float g_big[(size_t)MR * 1024];
__device__ __align__(256) hf g_b1h[(size_t)MR * 512];
__device__ __align__(256) hf g_b1l[(size_t)MR * 512];
__device__ __align__(256) hf g_xh [(size_t)MR * 1024];
__device__ __align__(256) hf g_xl [(size_t)MR * 1024];
__device__ __align__(256) hf g_xbh[(size_t)MR * 64];
__device__ __align__(256) hf g_xbl[(size_t)MR * 64];
__device__ __align__(256) hf g_wbh[1024 * 512];
__device__ __align__(256) hf g_wch[512 * 1024];
__device__ __align__(256) hf g_feh[1024 * 512];
__device__ __align__(256) hf g_fdh[512 * 512];
__device__ __align__(256) hf g_weh[512 * 64];
__device__ __align__(256) float2 g_lb[512];
__device__ __align__(256) float2 g_lbN[512];
__device__ __align__(256) float2 g_carry[NBATCH * NCHK * 512];
__device__ __align__(256) float g_pool[NBATCH * NCHK * 512];

__device__ __forceinline__ float geluf(float x) {
    return 0.5f * x * (1.0f + erff(x * 0.70710678118654752f));
}
__device__ __forceinline__ uint32_t s2u(const void* p) {
    uint32_t a;
    asm("{ .reg .u64 t; cvta.to.shared.u64 t, %1; cvt.u32.u64 %0, t; }" : "=r"(a) : "l"(p));
    return a;
}
__device__ __forceinline__ void split1(float v, hf* oh, hf* ol) {
    hf h = __float2half_rn(v);
    *oh = h;
    *ol = __float2half_rn(v - __half2float(h));
}
__device__ __forceinline__ void w1(float v, hf* oh) {
    *oh = __float2half_rn(v);
}
__device__ __forceinline__ uint32_t pack2(hf a, hf b) {
    union { hf h[2]; uint32_t u; } u;
    u.h[0] = a; u.h[1] = b;
    return u.u;
}
__device__ __forceinline__ void split4(float4 y, hf* oh, hf* ol) {
    union { hf b[4]; uint2 u; } H, L;
    float f[4] = {y.x, y.y, y.z, y.w};
#pragma unroll
    for (int e = 0; e < 4; e++) {
        hf h = __float2half_rn(f[e]);
        H.b[e] = h;
        L.b[e] = __float2half_rn(f[e] - __half2float(h));
    }
    *(uint2*)oh = H.u;
    *(uint2*)ol = L.u;
}
__device__ __forceinline__ float2 rec2(const hf* ph, const hf* pl) {
    __half2 hh = *(const __half2*)ph;
    __half2 ll = *(const __half2*)pl;
    return make_float2(__half2float(hh.x) + __half2float(ll.x),
                       __half2float(hh.y) + __half2float(ll.y));
}
__device__ __forceinline__ float2 cmul(float2 a, float2 b) {
    return make_float2(a.x * b.x - a.y * b.y, a.x * b.y + a.y * b.x);
}

#define LDSM4(r0, r1, r2, r3, a) \
    asm volatile("ldmatrix.sync.aligned.m8n8.x4.shared.b16 {%0,%1,%2,%3}, [%4];" \
                 : "=r"(r0), "=r"(r1), "=r"(r2), "=r"(r3) : "r"(a))

#define MMA16816(c, a0, a1, a2, a3, b0, b1) \
    asm volatile("mma.sync.aligned.m16n8k16.row.col.f32.f16.f16.f32 " \
                 "{%0,%1,%2,%3}, {%4,%5,%6,%7}, {%8,%9}, {%0,%1,%2,%3};" \
                 : "+f"((c)[0]), "+f"((c)[1]), "+f"((c)[2]), "+f"((c)[3]) \
                 : "r"(a0), "r"(a1), "r"(a2), "r"(a3), "r"(b0), "r"(b1))

// ---------------- HMMA GEMM: 128x128 block, BK=32, 3-stage swizzled -----------
// fp16 asymmetric: C = (Ah + Al) * Wh  -> 2 MMAs/tile, 3 smem matrices/stage.
#define MATB 8192
#define STG (3 * MATB)
#define GSMEM (3 * STG)
#define SCARRY_OFF 65536

__device__ __forceinline__ uint32_t swadr(uint32_t row, uint32_t c16) {
    return row * 64 + ((c16 ^ ((row >> 1) & 3)) << 4);
}

template <int EPI>
__global__ void __launch_bounds__(256, 2)
gemm_tc(const hf* __restrict__ Ah, const hf* __restrict__ Al, int lda,
        const hf* __restrict__ Wh, int K,
        float* __restrict__ C, int ldc,
        const float* __restrict__ vec,
        const hf* __restrict__ math, const hf* __restrict__ matl,
        hf* __restrict__ oh, hf* __restrict__ ol)
{
    extern __shared__ char smembuf[];
    const uint32_t sb = s2u(smembuf);
    const int tid = threadIdx.x, lane = tid & 31, wid = tid >> 5;
    const int warpM = wid & 3, warpN = wid >> 2;
    const int bm = blockIdx.y << 7, bn = blockIdx.x << 7;
    const int NCH = K >> 5;

    float c[2][8][4];
#pragma unroll
    for (int i = 0; i < 2; i++)
#pragma unroll
        for (int j = 0; j < 8; j++)
#pragma unroll
            for (int q = 0; q < 4; q++) c[i][j][q] = 0.f;

    auto LOAD = [&](int ch) {
        if (ch < NCH) {
            uint32_t base = sb + (ch % 3) * STG;
            const hf* gp[3] = {
                Ah + (size_t)bm * lda + ch * 32,
                Al + (size_t)bm * lda + ch * 32,
                Wh + (size_t)bn * K + ch * 32 };
            const int ld3[3] = {lda, lda, K};
#pragma unroll
            for (int mt = 0; mt < 3; mt++) {
                uint32_t mb = base + mt * MATB;
                const hf* g = gp[mt];
                int ld = ld3[mt];
#pragma unroll
                for (int q = 0; q < 2; q++) {
                    int idx = tid + q * 256;
                    uint32_t row = idx >> 2, c16 = idx & 3;
                    uint32_t d = mb + swadr(row, c16);
                    const hf* src = g + (size_t)row * ld + c16 * 8;
                    asm volatile("cp.async.cg.shared.global [%0], [%1], 16;"
                                 :: "r"(d), "l"(src) : "memory");
                }
            }
        }
        asm volatile("cp.async.commit_group;" ::: "memory");
    };

    LOAD(0); LOAD(1);

    for (int ch = 0; ch < NCH; ch++) {
        asm volatile("cp.async.wait_group 1;" ::: "memory");
        __syncthreads();
        LOAD(ch + 2);

        uint32_t base = sb + (ch % 3) * STG;
#pragma unroll
        for (int kk = 0; kk < 2; kk++) {
            uint32_t c16 = kk * 2 + (lane >> 4);
            uint32_t ah[2][4], al[2][4];
#pragma unroll
            for (int mf = 0; mf < 2; mf++) {
                uint32_t row = warpM * 32 + mf * 16 + (lane & 15);
                uint32_t a0 = base + swadr(row, c16);
                LDSM4(ah[mf][0], ah[mf][1], ah[mf][2], ah[mf][3], a0);
                LDSM4(al[mf][0], al[mf][1], al[mf][2], al[mf][3], a0 + MATB);
            }
#pragma unroll
            for (int g = 0; g < 4; g++) {
                uint32_t row = warpN * 64 + g * 16 + (lane & 15);
                uint32_t a0 = base + 2 * MATB + swadr(row, c16);
                uint32_t h0, h1, h2, h3;
                LDSM4(h0, h1, h2, h3, a0);
#pragma unroll
                for (int mf = 0; mf < 2; mf++) {
                    MMA16816(c[mf][2*g],   ah[mf][0], ah[mf][1], ah[mf][2], ah[mf][3], h0, h2);
                    MMA16816(c[mf][2*g+1], ah[mf][0], ah[mf][1], ah[mf][2], ah[mf][3], h1, h3);
                }
#pragma unroll
                for (int mf = 0; mf < 2; mf++) {
                    MMA16816(c[mf][2*g],   al[mf][0], al[mf][1], al[mf][2], al[mf][3], h0, h2);
                    MMA16816(c[mf][2*g+1], al[mf][0], al[mf][1], al[mf][2], al[mf][3], h1, h3);
                }
            }
        }
    }

    if (EPI == 5) {
        // parallel segmented scan: 64 complex chains x 4 segments of 32 steps
        float* sc = (float*)smembuf;
        float2* scar = (float2*)(smembuf + SCARRY_OFF);
        __syncthreads();
#pragma unroll
        for (int mf = 0; mf < 2; mf++) {
            int r0 = warpM * 32 + mf * 16 + (lane >> 2);
#pragma unroll
            for (int jb = 0; jb < 8; jb++) {
                int n = warpN * 64 + jb * 8 + 2 * (lane & 3);
#pragma unroll
                for (int half = 0; half < 2; half++) {
                    *(float2*)&sc[(r0 + half * 8) * 128 + n] =
                        make_float2(c[mf][jb][2 * half], c[mf][jb][2 * half + 1]);
                }
            }
        }
        __syncthreads();
        {
            int j = tid & 63, seg = tid >> 6;
            int t0 = seg * 32;
            int pglob = (bn >> 1) + j;
            float2 lb = g_lb[pglob];
            float xr = 0.f, xi = 0.f;
#pragma unroll 4
            for (int t = 0; t < 32; t++) {
                float2* pp = (float2*)&sc[(t0 + t) * 128 + 2 * j];
                float2 bu = *pp;
                float nr = fmaf(lb.x, xr, fmaf(-lb.y, xi, bu.x));
                float ni = fmaf(lb.x, xi, fmaf(lb.y, xr, bu.y));
                xr = nr; xi = ni;
                *pp = make_float2(xr, xi);
            }
            scar[seg * 64 + j] = make_float2(xr, xi);
            __syncthreads();
            float2 pw32 = lb;
#pragma unroll
            for (int q = 0; q < 5; q++) pw32 = cmul(pw32, pw32);
            float2 s = make_float2(0.f, 0.f);
            for (int k = 0; k < seg; k++) {
                float2 ck = scar[k * 64 + j];
                float nr = fmaf(pw32.x, s.x, fmaf(-pw32.y, s.y, ck.x));
                float ni = fmaf(pw32.x, s.y, fmaf(pw32.y, s.x, ck.y));
                s = make_float2(nr, ni);
            }
            float* outp = g_big + (size_t)(bm + t0) * 1024 + bn + 2 * j;
            float2 pw = lb;
            float2 last = make_float2(0.f, 0.f);
#pragma unroll 4
            for (int t = 0; t < 32; t++) {
                float2 l = *(float2*)&sc[(t0 + t) * 128 + 2 * j];
                float2 v = make_float2(fmaf(pw.x, s.x, fmaf(-pw.y, s.y, l.x)),
                                       fmaf(pw.x, s.y, fmaf(pw.y, s.x, l.y)));
                *(float2*)(outp + (size_t)t * 1024) = v;
                pw = cmul(pw, lb);
                last = v;
            }
            if (seg == 3) {
                int b = bm >> 12, cch = (bm >> 7) & 31;
                g_carry[((size_t)b * NCHK + cch) * 512 + pglob] = last;
            }
        }
        return;
    }

#pragma unroll
    for (int mf = 0; mf < 2; mf++) {
        int m0 = bm + warpM * 32 + mf * 16 + (lane >> 2);
#pragma unroll
        for (int jb = 0; jb < 8; jb++) {
            int n = bn + warpN * 64 + jb * 8 + 2 * (lane & 3);
#pragma unroll
            for (int half = 0; half < 2; half++) {
                int r = m0 + half * 8;
                float v0 = c[mf][jb][2 * half], v1 = c[mf][jb][2 * half + 1];
                if (EPI == 4) {
                    int j = ((bn + warpN * 64 + jb * 8) >> 1) + (lane & 3);
                    size_t off = (size_t)r * 512 + j;
                    split1(v0 * geluf(v1), oh + off, ol + off);
                } else {
                    size_t off = (size_t)r * ldc + n;
                    if (EPI == 1) {
                        float2 bv = *(const float2*)(vec + n);
                        v0 += bv.x; v1 += bv.y;
                    } else if (EPI == 2) {
                        float2 u = rec2(math + (size_t)r * 512 + n, matl + (size_t)r * 512 + n);
                        float2 dv = *(const float2*)(vec + n);
                        v0 = geluf(v0 + dv.x * u.x) + u.x;
                        v1 = geluf(v1 + dv.y * u.y) + u.y;
                    } else if (EPI == 3) {
                        float2 u = rec2(math + (size_t)r * 512 + n, matl + (size_t)r * 512 + n);
                        float2 co = *(const float2*)(C + off);
                        v0 += co.x + u.x; v1 += co.y + u.y;
                    }
                    *(float2*)(C + off) = make_float2(v0, v1);
                }
            }
        }
    }
}

// ---------------- LayerNorm (warp per row) ----------------
__device__ __forceinline__ float wsum(float x) {
#pragma unroll
    for (int o = 16; o; o >>= 1) x += __shfl_xor_sync(0xFFFFFFFFu, x, o);
    return x;
}
__device__ __forceinline__ void ln_stage(float4 v[4], const float* __restrict__ w,
                                         const float* __restrict__ b, int l) {
    float s = 0.f;
#pragma unroll
    for (int q = 0; q < 4; q++) s += v[q].x + v[q].y + v[q].z + v[q].w;
    float mean = wsum(s) * (1.f / 512.f);
    float vv = 0.f;
#pragma unroll
    for (int q = 0; q < 4; q++) {
        v[q].x -= mean; v[q].y -= mean; v[q].z -= mean; v[q].w -= mean;
        vv += v[q].x * v[q].x + v[q].y * v[q].y + v[q].z * v[q].z + v[q].w * v[q].w;
    }
    float rs = rsqrtf(wsum(vv) * (1.f / 512.f) + 1e-5f);
#pragma unroll
    for (int q = 0; q < 4; q++) {
        int cc = (l + q * 32) * 4;
        float4 wf = *(const float4*)(w + cc);
        float4 bf = *(const float4*)(b + cc);
        v[q].x = v[q].x * rs * wf.x + bf.x;
        v[q].y = v[q].y * rs * wf.y + bf.y;
        v[q].z = v[q].z * rs * wf.z + bf.z;
        v[q].w = v[q].w * rs * wf.w + bf.w;
    }
}

template <int TWO>
__global__ void __launch_bounds__(256)
ln_kernel(const float* __restrict__ in,
          hf* __restrict__ oh, hf* __restrict__ ol,
          const float* __restrict__ w1v, const float* __restrict__ b1,
          const float* __restrict__ w2, const float* __restrict__ b2)
{
    int row = blockIdx.x * 8 + (threadIdx.x >> 5);
    int l = threadIdx.x & 31;
    const float4* xr = (const float4*)(in + (size_t)row * 512);
    float4 v[4];
#pragma unroll
    for (int q = 0; q < 4; q++) v[q] = xr[l + q * 32];
    ln_stage(v, w1v, b1, l);
    if (TWO) ln_stage(v, w2, b2, l);
#pragma unroll
    for (int q = 0; q < 4; q++) {
        size_t off = (size_t)row * 512 + (size_t)(l + q * 32) * 4;
        split4(v[q], oh + off, ol + off);
    }
}

// ---------------- per-layer prep ----------------
__device__ __forceinline__ float2 coef_of(float lr, float li, float lstep,
                                          float* lbx, float* lby)
{
    float st = expf(lstep);
    float er = expf(lr * st);
    float cc = er * cosf(li * st);
    float ss = er * sinf(li * st);
    *lbx = cc; *lby = ss;
    float den = lr * lr + li * li;
    return make_float2(((cc - 1.f) * lr + ss * li) / den, (ss * lr - (cc - 1.f) * li) / den);
}

__device__ __forceinline__ void prep_layer_body(int blk, int tid,
                           const float* __restrict__ lam_re, const float* __restrict__ lam_im,
                           const float* __restrict__ log_step,
                           const float* __restrict__ Bre, const float* __restrict__ Bim,
                           const float* __restrict__ Cre, const float* __restrict__ Cim,
                           const float* __restrict__ ffe, const float* __restrict__ ffd)
{
    if (blk < 1024) {
        int idx = blk * 256 + tid;
        int p = idx >> 9, d = idx & 511;
        float lbx, lby;
        float2 cf = coef_of(lam_re[p], lam_im[p], log_step[p], &lbx, &lby);
        float br = Bre[idx], bi = Bim[idx];
        w1(cf.x * br - cf.y * bi, &g_wbh[(size_t)(2 * p) * 512 + d]);
        w1(cf.x * bi + cf.y * br, &g_wbh[(size_t)(2 * p + 1) * 512 + d]);
    } else if (blk < 2048) {
        int idx = (blk - 1024) * 256 + tid;
        int d = idx >> 9, p = idx & 511;
        w1(2.f * Cre[idx], &g_wch[(size_t)d * 1024 + 2 * p]);
        w1(-2.f * Cim[idx], &g_wch[(size_t)d * 1024 + 2 * p + 1]);
    } else if (blk < 4096) {
        int idx = (blk - 2048) * 256 + tid;
        int r = idx >> 9, k = idx & 511;
        int src = (r & 1) ? (512 + (r >> 1)) : (r >> 1);
        w1(ffe[(size_t)src * 512 + k], &g_feh[(size_t)r * 512 + k]);
    } else if (blk < 5120) {
        int idx = (blk - 4096) * 256 + tid;
        w1(ffd[idx], &g_fdh[idx]);
    } else {
        int p = (blk - 5120) * 256 + tid;
        float lbx, lby;
        coef_of(lam_re[p], lam_im[p], log_step[p], &lbx, &lby);
        g_lb[p] = make_float2(lbx, lby);
        float ar = lbx, ai = lby;
#pragma unroll
        for (int i = 0; i < 7; i++) {
            float nr = ar * ar - ai * ai, ni = 2.f * ar * ai;
            ar = nr; ai = ni;
        }
        g_lbN[p] = make_float2(ar, ai);
    }
}

__global__ void prep_layer(const float* __restrict__ lam_re, const float* __restrict__ lam_im,
                           const float* __restrict__ log_step,
                           const float* __restrict__ Bre, const float* __restrict__ Bim,
                           const float* __restrict__ Cre, const float* __restrict__ Cim,
                           const float* __restrict__ ffe, const float* __restrict__ ffd)
{
    prep_layer_body(blockIdx.x, threadIdx.x, lam_re, lam_im, log_step,
                    Bre, Bim, Cre, Cim, ffe, ffd);
}

__global__ void prep_all(const float* __restrict__ x, const float* __restrict__ enc_w,
                         const float* __restrict__ lam_re, const float* __restrict__ lam_im,
                         const float* __restrict__ log_step,
                         const float* __restrict__ Bre, const float* __restrict__ Bim,
                         const float* __restrict__ Cre, const float* __restrict__ Cim,
                         const float* __restrict__ ffe, const float* __restrict__ ffd)
{
    int blk = blockIdx.x, tid = threadIdx.x;
    if (blk < 2048) {
        int idx = blk * 256 + tid;
        int mrow = idx >> 4, q = idx & 15;
        float4 v = *(const float4*)(x + (size_t)mrow * 64 + q * 4);
        size_t off = (size_t)mrow * 64 + (size_t)q * 4;
        split4(v, g_xbh + off, g_xbl + off);
    } else if (blk < 2176) {
        int idx = (blk - 2048) * 256 + tid;
        int k = idx >> 9, n = idx & 511;
        w1(enc_w[idx], &g_weh[(size_t)n * 64 + k]);
    } else {
        prep_layer_body(blk - 2176, tid, lam_re, lam_im, log_step,
                        Bre, Bim, Cre, Cim, ffe, ffd);
    }
}

// ---------------- scan pass3 (carry combine folded in) ----------------
__global__ void scan_pass3()
{
    const int p = threadIdx.x;
    const int c = blockIdx.x, b = blockIdx.y;
    float2 lb = g_lb[p];
    float2 A = g_lbN[p];
    float2 cv = make_float2(0.f, 0.f);
    for (int k = 0; k < c; k++) {
        float2 ck = g_carry[((size_t)b * NCHK + k) * 512 + p];
        float nr = fmaf(A.x, cv.x, fmaf(-A.y, cv.y, ck.x));
        float ni = fmaf(A.x, cv.y, fmaf(A.y, cv.x, ck.y));
        cv = make_float2(nr, ni);
    }
    float pr = lb.x, pi = lb.y;
    size_t row0 = (size_t)(b * LSEQ + c * CLEN);
    const float2* loc = (const float2*)(g_big + row0 * 1024) + p;
    uint32_t* xh = (uint32_t*)(g_xh + row0 * 1024) + p;
    uint32_t* xl = (uint32_t*)(g_xl + row0 * 1024) + p;
    for (int t = 0; t < CLEN; t++) {
        float2 l = loc[(size_t)t * 512];
        float xr = fmaf(pr, cv.x, fmaf(-pi, cv.y, l.x));
        float xi = fmaf(pr, cv.y, fmaf(pi, cv.x, l.y));
        float nr = pr * lb.x - pi * lb.y;
        pi = pr * lb.y + pi * lb.x; pr = nr;
        hf hr = __float2half_rn(xr);
        hf hi2 = __float2half_rn(xi);
        xh[(size_t)t * 512] = pack2(hr, hi2);
        xl[(size_t)t * 512] = pack2(__float2half_rn(xr - __half2float(hr)),
                                    __float2half_rn(xi - __half2float(hi2)));
    }
}

// ---------------- pool (2-stage) + head ----------------
__global__ void pool_partial(const int* __restrict__ lengths)
{
    const int b = blockIdx.x, c = blockIdx.y;
    const int d = threadIdx.x;
    int len = lengths[b];
    int t0 = c * CLEN;
    int t1 = t0 + CLEN < len ? t0 + CLEN : len;
    float s = 0.f;
    const float* hp = g_h + ((size_t)(b * LSEQ + t0)) * 512 + d;
    for (int t = t0; t < t1; t++) { s += hp[0]; hp += 512; }
    g_pool[((size_t)b * NCHK + c) * 512 + d] = s;
}

__global__ void pool_head(const int* __restrict__ lengths,
                          const float* __restrict__ hw, const float* __restrict__ hb,
                          float* __restrict__ out)
{
    const int b = blockIdx.x;
    const int d = threadIdx.x;
    float s = 0.f;
#pragma unroll
    for (int c = 0; c < NCHK; c++) s += g_pool[((size_t)b * NCHK + c) * 512 + d];
    int len = lengths[b];
    int den = len > 1 ? len : 1;
    float v = (s / (float)den) * hw[d];
    __shared__ float red[512];
    red[d] = v; __syncthreads();
    for (int st = 256; st > 0; st >>= 1) { if (d < st) red[d] += red[d + st]; __syncthreads(); }
    if (d == 0) out[b] = red[0] + hb[0];
}

// ---------------- launch ----------------
extern "C" void kernel_launch(void* const* d_in, const int* in_sizes, int n_in,
                              void* d_out, int out_size)
{
    const float* x       = (const float*)d_in[0];
    const int*   lengths = (const int*)  d_in[1];
    const float* enc_w   = (const float*)d_in[2];
    const float* enc_b   = (const float*)d_in[3];
    const float* lam_re  = (const float*)d_in[4];
    const float* lam_im  = (const float*)d_in[5];
    const float* Bre     = (const float*)d_in[6];
    const float* Bim     = (const float*)d_in[7];
    const float* Cre     = (const float*)d_in[8];
    const float* Cim     = (const float*)d_in[9];
    const float* Dp      = (const float*)d_in[10];
    const float* log_step= (const float*)d_in[11];
    const float* an_w    = (const float*)d_in[12];
    const float* an_b    = (const float*)d_in[13];
    const float* fn_w    = (const float*)d_in[14];
    const float* fn_b    = (const float*)d_in[15];
    const float* ffe_w   = (const float*)d_in[16];
    const float* ffd_w   = (const float*)d_in[17];
    const float* norm_w  = (const float*)d_in[18];
    const float* norm_b  = (const float*)d_in[19];
    const float* head_w  = (const float*)d_in[20];
    const float* head_b  = (const float*)d_in[21];
    float* out = (float*)d_out;

    cudaFuncSetAttribute(gemm_tc<1>, cudaFuncAttributeMaxDynamicSharedMemorySize, GSMEM);
    cudaFuncSetAttribute(gemm_tc<2>, cudaFuncAttributeMaxDynamicSharedMemorySize, GSMEM);
    cudaFuncSetAttribute(gemm_tc<3>, cudaFuncAttributeMaxDynamicSharedMemorySize, GSMEM);
    cudaFuncSetAttribute(gemm_tc<4>, cudaFuncAttributeMaxDynamicSharedMemorySize, GSMEM);
    cudaFuncSetAttribute(gemm_tc<5>, cudaFuncAttributeMaxDynamicSharedMemorySize, GSMEM);

    void *p_h, *p_b2, *p_big, *p_b1h, *p_b1l, *p_xh, *p_xl, *p_xbh, *p_xbl;
    void *p_wbh, *p_wch, *p_feh, *p_fdh, *p_weh;
    cudaGetSymbolAddress(&p_h, g_h);
    cudaGetSymbolAddress(&p_b2, g_b2);   cudaGetSymbolAddress(&p_big, g_big);
    cudaGetSymbolAddress(&p_b1h, g_b1h); cudaGetSymbolAddress(&p_b1l, g_b1l);
    cudaGetSymbolAddress(&p_xh, g_xh);   cudaGetSymbolAddress(&p_xl, g_xl);
    cudaGetSymbolAddress(&p_xbh, g_xbh); cudaGetSymbolAddress(&p_xbl, g_xbl);
    cudaGetSymbolAddress(&p_wbh, g_wbh); cudaGetSymbolAddress(&p_wch, g_wch);
    cudaGetSymbolAddress(&p_feh, g_feh); cudaGetSymbolAddress(&p_fdh, g_fdh);
    cudaGetSymbolAddress(&p_weh, g_weh);
    float* h   = (float*)p_h;
    float* b2  = (float*)p_b2; float* big = (float*)p_big;
    hf* b1h = (hf*)p_b1h; hf* b1l = (hf*)p_b1l;
    hf* xh  = (hf*)p_xh;  hf* xl  = (hf*)p_xl;
    hf* xbh = (hf*)p_xbh; hf* xbl = (hf*)p_xbl;
    hf* wbh = (hf*)p_wbh; hf* wch = (hf*)p_wch;
    hf* feh = (hf*)p_feh; hf* fdh = (hf*)p_fdh;
    hf* weh = (hf*)p_weh;

    prep_all<<<7298, 256>>>(x, enc_w, lam_re, lam_im, log_step,
                            Bre, Bim, Cre, Cim, ffe_w, ffd_w);
    gemm_tc<1><<<dim3(4, 256), 256, GSMEM>>>(xbh, xbl, 64, weh, 64,
                                             h, 512, enc_b, nullptr, nullptr, nullptr, nullptr);

    for (int i = 0; i < NLAYER; i++) {
        if (i > 0)
            prep_layer<<<5122, 256>>>(lam_re + i * 512, lam_im + i * 512, log_step + i * 512,
                                      Bre + (size_t)i * 512 * 512, Bim + (size_t)i * 512 * 512,
                                      Cre + (size_t)i * 512 * 512, Cim + (size_t)i * 512 * 512,
                                      ffe_w + (size_t)i * 1024 * 512, ffd_w + (size_t)i * 512 * 512);
        ln_kernel<1><<<MR / 8, 256>>>(h, b1h, b1l,
                                      norm_w + i * 512, norm_b + i * 512,
                                      an_w + i * 512, an_b + i * 512);
        // launch #4 (i=0): Bu GEMM + fused parallel chunk scan  <- ncu capture target
        gemm_tc<5><<<dim3(8, 256), 256, GSMEM>>>(b1h, b1l, 512, wbh, 512,
                                                 big, 1024, nullptr, nullptr, nullptr, nullptr, nullptr);
        scan_pass3<<<dim3(NCHK, NBATCH), 512>>>();
        gemm_tc<2><<<dim3(4, 256), 256, GSMEM>>>(xh, xl, 1024, wch, 1024,
                                                 b2, 512, Dp + i * 512, b1h, b1l, nullptr, nullptr);
        ln_kernel<0><<<MR / 8, 256>>>(b2, b1h, b1l, fn_w + i * 512, fn_b + i * 512,
                                      nullptr, nullptr);
        gemm_tc<4><<<dim3(8, 256), 256, GSMEM>>>(b1h, b1l, 512, feh, 512,
                                                 nullptr, 512, nullptr, nullptr, nullptr, xh, xl);
        gemm_tc<3><<<dim3(4, 256), 256, GSMEM>>>(xh, xl, 512, fdh, 512,
                                                 h, 512, nullptr, b1h, b1l, nullptr, nullptr);
    }

    pool_partial<<<dim3(NBATCH, NCHK), 512>>>(lengths);
    pool_head<<<NBATCH, 512>>>(lengths, head_w, head_b, out);
}

// round 14
// speedup vs baseline: 1.4551x; 1.0832x over previous
#include <cuda_runtime.h>
#include <cuda_fp16.h>
#include <math.h>
#include <stdint.h>

#define MR 32768
#define LSEQ 4096
#define NBATCH 8
#define NLAYER 3
#define NCHK 32
#define CLEN 128

typedef __half hf;

// ---------------- scratch ----------------
__device__ __align__(256) float g_h  [(size_t)MR * 512];
__device__ __align__(256) float g_b2 [(size_t)MR * 512];
__device__ __align__(256) float g_big[(size_t)MR * 1024];
__device__ __align__(256) hf g_b1h[(size_t)MR * 512];
__device__ __align__(256) hf g_b1l[(size_t)MR * 512];
__device__ __align__(256) hf g_xh [(size_t)MR * 1024];
__device__ __align__(256) hf g_xl [(size_t)MR * 1024];
__device__ __align__(256) hf g_xbh[(size_t)MR * 64];
__device__ __align__(256) hf g_xbl[(size_t)MR * 64];
__device__ __align__(256) hf g_wbh[1024 * 512];
__device__ __align__(256) hf g_wch[512 * 1024];
__device__ __align__(256) hf g_feh[1024 * 512];
__device__ __align__(256) hf g_fdh[512 * 512];
__device__ __align__(256) hf g_weh[512 * 64];
__device__ __align__(256) float2 g_lb[512];
__device__ __align__(256) float2 g_lbN[512];
__device__ __align__(256) float2 g_carry[NBATCH * NCHK * 512];
__device__ __align__(256) float g_pool[NBATCH * NCHK * 512];

__device__ __forceinline__ float geluf(float x) {
    return 0.5f * x * (1.0f + erff(x * 0.70710678118654752f));
}
__device__ __forceinline__ uint32_t s2u(const void* p) {
    uint32_t a;
    asm("{ .reg .u64 t; cvta.to.shared.u64 t, %1; cvt.u32.u64 %0, t; }" : "=r"(a) : "l"(p));
    return a;
}
__device__ __forceinline__ void split1(float v, hf* oh, hf* ol) {
    hf h = __float2half_rn(v);
    *oh = h;
    *ol = __float2half_rn(v - __half2float(h));
}
__device__ __forceinline__ void w1(float v, hf* oh) {
    *oh = __float2half_rn(v);
}
__device__ __forceinline__ uint32_t pack2(hf a, hf b) {
    union { hf h[2]; uint32_t u; } u;
    u.h[0] = a; u.h[1] = b;
    return u.u;
}
__device__ __forceinline__ void split4(float4 y, hf* oh, hf* ol) {
    union { hf b[4]; uint2 u; } H, L;
    float f[4] = {y.x, y.y, y.z, y.w};
#pragma unroll
    for (int e = 0; e < 4; e++) {
        hf h = __float2half_rn(f[e]);
        H.b[e] = h;
        L.b[e] = __float2half_rn(f[e] - __half2float(h));
    }
    *(uint2*)oh = H.u;
    *(uint2*)ol = L.u;
}
__device__ __forceinline__ float2 rec2(const hf* ph, const hf* pl) {
    __half2 hh = *(const __half2*)ph;
    __half2 ll = *(const __half2*)pl;
    return make_float2(__half2float(hh.x) + __half2float(ll.x),
                       __half2float(hh.y) + __half2float(ll.y));
}
__device__ __forceinline__ float2 cmul(float2 a, float2 b) {
    return make_float2(a.x * b.x - a.y * b.y, a.x * b.y + a.y * b.x);
}

#define LDSM4(r0, r1, r2, r3, a) \
    asm volatile("ldmatrix.sync.aligned.m8n8.x4.shared.b16 {%0,%1,%2,%3}, [%4];" \
                 : "=r"(r0), "=r"(r1), "=r"(r2), "=r"(r3) : "r"(a))

#define MMA16816(c, a0, a1, a2, a3, b0, b1) \
    asm volatile("mma.sync.aligned.m16n8k16.row.col.f32.f16.f16.f32 " \
                 "{%0,%1,%2,%3}, {%4,%5,%6,%7}, {%8,%9}, {%0,%1,%2,%3};" \
                 : "+f"((c)[0]), "+f"((c)[1]), "+f"((c)[2]), "+f"((c)[3]) \
                 : "r"(a0), "r"(a1), "r"(a2), "r"(a3), "r"(b0), "r"(b1))

// ---------------- HMMA GEMM: 128x128 block, BK=64, 2-stage swizzled, 2 blocks/SM ---
// fp16 asymmetric: C = (Ah + Al) * Wh. 3 smem matrices (Ah, Al, Wh), 16 KB each.
#define MATB 16384
#define STG (3 * MATB)
#define GSMEM (2 * STG)
#define SCARRY_OFF 65536

__device__ __forceinline__ uint32_t swadr(uint32_t row, uint32_t c16) {
    return row * 128 + ((c16 ^ (row & 7)) << 4);
}

template <int EPI>
__global__ void __launch_bounds__(256, 2)
gemm_tc(const hf* __restrict__ Ah, const hf* __restrict__ Al, int lda,
        const hf* __restrict__ Wh, int K,
        float* __restrict__ C, int ldc,
        const float* __restrict__ vec,
        const hf* __restrict__ math, const hf* __restrict__ matl,
        hf* __restrict__ oh, hf* __restrict__ ol)
{
    extern __shared__ char smembuf[];
    const uint32_t sb = s2u(smembuf);
    const int tid = threadIdx.x, lane = tid & 31, wid = tid >> 5;
    const int warpM = wid & 3, warpN = wid >> 2;
    const int bm = blockIdx.y << 7, bn = blockIdx.x << 7;
    const int NCH = K >> 6;

    float c[2][8][4];
#pragma unroll
    for (int i = 0; i < 2; i++)
#pragma unroll
        for (int j = 0; j < 8; j++)
#pragma unroll
            for (int q = 0; q < 4; q++) c[i][j][q] = 0.f;

    auto LOAD = [&](int ch) {
        if (ch < NCH) {
            uint32_t base = sb + (ch & 1) * STG;
            const hf* gp[3] = {
                Ah + (size_t)bm * lda + ch * 64,
                Al + (size_t)bm * lda + ch * 64,
                Wh + (size_t)bn * K + ch * 64 };
            const int ld3[3] = {lda, lda, K};
#pragma unroll
            for (int mt = 0; mt < 3; mt++) {
                uint32_t mb = base + mt * MATB;
                const hf* g = gp[mt];
                int ld = ld3[mt];
#pragma unroll
                for (int q = 0; q < 4; q++) {
                    int idx = tid + q * 256;
                    uint32_t row = idx >> 3, c16 = idx & 7;
                    uint32_t d = mb + swadr(row, c16);
                    const hf* src = g + (size_t)row * ld + c16 * 8;
                    asm volatile("cp.async.cg.shared.global [%0], [%1], 16;"
                                 :: "r"(d), "l"(src) : "memory");
                }
            }
        }
        asm volatile("cp.async.commit_group;" ::: "memory");
    };

    LOAD(0);

    for (int ch = 0; ch < NCH; ch++) {
        asm volatile("cp.async.wait_group 0;" ::: "memory");
        __syncthreads();           // all warps done with buffer (ch+1)&1 from iter ch-1
        LOAD(ch + 1);              // safe: targets the buffer consumed in iter ch-1

        uint32_t base = sb + (ch & 1) * STG;
#pragma unroll
        for (int kk = 0; kk < 4; kk++) {
            uint32_t c16 = kk * 2 + (lane >> 4);
            uint32_t ah[2][4], al[2][4];
#pragma unroll
            for (int mf = 0; mf < 2; mf++) {
                uint32_t row = warpM * 32 + mf * 16 + (lane & 15);
                uint32_t a0 = base + swadr(row, c16);
                LDSM4(ah[mf][0], ah[mf][1], ah[mf][2], ah[mf][3], a0);
                LDSM4(al[mf][0], al[mf][1], al[mf][2], al[mf][3], a0 + MATB);
            }
#pragma unroll
            for (int g = 0; g < 4; g++) {
                uint32_t row = warpN * 64 + g * 16 + (lane & 15);
                uint32_t a0 = base + 2 * MATB + swadr(row, c16);
                uint32_t h0, h1, h2, h3;
                LDSM4(h0, h1, h2, h3, a0);
#pragma unroll
                for (int mf = 0; mf < 2; mf++) {
                    MMA16816(c[mf][2*g],   ah[mf][0], ah[mf][1], ah[mf][2], ah[mf][3], h0, h2);
                    MMA16816(c[mf][2*g+1], ah[mf][0], ah[mf][1], ah[mf][2], ah[mf][3], h1, h3);
                }
#pragma unroll
                for (int mf = 0; mf < 2; mf++) {
                    MMA16816(c[mf][2*g],   al[mf][0], al[mf][1], al[mf][2], al[mf][3], h0, h2);
                    MMA16816(c[mf][2*g+1], al[mf][0], al[mf][1], al[mf][2], al[mf][3], h1, h3);
                }
            }
        }
    }

    if (EPI == 5) {
        // parallel segmented scan: 64 complex chains x 4 segments of 32 steps
        float* sc = (float*)smembuf;
        float2* scar = (float2*)(smembuf + SCARRY_OFF);
        __syncthreads();
#pragma unroll
        for (int mf = 0; mf < 2; mf++) {
            int r0 = warpM * 32 + mf * 16 + (lane >> 2);
#pragma unroll
            for (int jb = 0; jb < 8; jb++) {
                int n = warpN * 64 + jb * 8 + 2 * (lane & 3);
#pragma unroll
                for (int half = 0; half < 2; half++) {
                    *(float2*)&sc[(r0 + half * 8) * 128 + n] =
                        make_float2(c[mf][jb][2 * half], c[mf][jb][2 * half + 1]);
                }
            }
        }
        __syncthreads();
        {
            int j = tid & 63, seg = tid >> 6;
            int t0 = seg * 32;
            int pglob = (bn >> 1) + j;
            float2 lb = g_lb[pglob];
            float xr = 0.f, xi = 0.f;
#pragma unroll 4
            for (int t = 0; t < 32; t++) {
                float2* pp = (float2*)&sc[(t0 + t) * 128 + 2 * j];
                float2 bu = *pp;
                float nr = fmaf(lb.x, xr, fmaf(-lb.y, xi, bu.x));
                float ni = fmaf(lb.x, xi, fmaf(lb.y, xr, bu.y));
                xr = nr; xi = ni;
                *pp = make_float2(xr, xi);
            }
            scar[seg * 64 + j] = make_float2(xr, xi);
            __syncthreads();
            float2 pw32 = lb;
#pragma unroll
            for (int q = 0; q < 5; q++) pw32 = cmul(pw32, pw32);
            float2 s = make_float2(0.f, 0.f);
            for (int k = 0; k < seg; k++) {
                float2 ck = scar[k * 64 + j];
                float nr = fmaf(pw32.x, s.x, fmaf(-pw32.y, s.y, ck.x));
                float ni = fmaf(pw32.x, s.y, fmaf(pw32.y, s.x, ck.y));
                s = make_float2(nr, ni);
            }
            float* outp = g_big + (size_t)(bm + t0) * 1024 + bn + 2 * j;
            float2 pw = lb;
            float2 last = make_float2(0.f, 0.f);
#pragma unroll 4
            for (int t = 0; t < 32; t++) {
                float2 l = *(float2*)&sc[(t0 + t) * 128 + 2 * j];
                float2 v = make_float2(fmaf(pw.x, s.x, fmaf(-pw.y, s.y, l.x)),
                                       fmaf(pw.x, s.y, fmaf(pw.y, s.x, l.y)));
                *(float2*)(outp + (size_t)t * 1024) = v;
                pw = cmul(pw, lb);
                last = v;
            }
            if (seg == 3) {
                int b = bm >> 12, cch = (bm >> 7) & 31;
                g_carry[((size_t)b * NCHK + cch) * 512 + pglob] = last;
            }
        }
        return;
    }

#pragma unroll
    for (int mf = 0; mf < 2; mf++) {
        int m0 = bm + warpM * 32 + mf * 16 + (lane >> 2);
#pragma unroll
        for (int jb = 0; jb < 8; jb++) {
            int n = bn + warpN * 64 + jb * 8 + 2 * (lane & 3);
#pragma unroll
            for (int half = 0; half < 2; half++) {
                int r = m0 + half * 8;
                float v0 = c[mf][jb][2 * half], v1 = c[mf][jb][2 * half + 1];
                if (EPI == 4) {
                    int j = ((bn + warpN * 64 + jb * 8) >> 1) + (lane & 3);
                    size_t off = (size_t)r * 512 + j;
                    split1(v0 * geluf(v1), oh + off, ol + off);
                } else {
                    size_t off = (size_t)r * ldc + n;
                    if (EPI == 1) {
                        float2 bv = *(const float2*)(vec + n);
                        v0 += bv.x; v1 += bv.y;
                    } else if (EPI == 2) {
                        float2 u = rec2(math + (size_t)r * 512 + n, matl + (size_t)r * 512 + n);
                        float2 dv = *(const float2*)(vec + n);
                        v0 = geluf(v0 + dv.x * u.x) + u.x;
                        v1 = geluf(v1 + dv.y * u.y) + u.y;
                    } else if (EPI == 3) {
                        float2 u = rec2(math + (size_t)r * 512 + n, matl + (size_t)r * 512 + n);
                        float2 co = *(const float2*)(C + off);
                        v0 += co.x + u.x; v1 += co.y + u.y;
                    }
                    *(float2*)(C + off) = make_float2(v0, v1);
                }
            }
        }
    }
}

// ---------------- LayerNorm (warp per row) ----------------
__device__ __forceinline__ float wsum(float x) {
#pragma unroll
    for (int o = 16; o; o >>= 1) x += __shfl_xor_sync(0xFFFFFFFFu, x, o);
    return x;
}
__device__ __forceinline__ void ln_stage(float4 v[4], const float* __restrict__ w,
                                         const float* __restrict__ b, int l) {
    float s = 0.f;
#pragma unroll
    for (int q = 0; q < 4; q++) s += v[q].x + v[q].y + v[q].z + v[q].w;
    float mean = wsum(s) * (1.f / 512.f);
    float vv = 0.f;
#pragma unroll
    for (int q = 0; q < 4; q++) {
        v[q].x -= mean; v[q].y -= mean; v[q].z -= mean; v[q].w -= mean;
        vv += v[q].x * v[q].x + v[q].y * v[q].y + v[q].z * v[q].z + v[q].w * v[q].w;
    }
    float rs = rsqrtf(wsum(vv) * (1.f / 512.f) + 1e-5f);
#pragma unroll
    for (int q = 0; q < 4; q++) {
        int cc = (l + q * 32) * 4;
        float4 wf = *(const float4*)(w + cc);
        float4 bf = *(const float4*)(b + cc);
        v[q].x = v[q].x * rs * wf.x + bf.x;
        v[q].y = v[q].y * rs * wf.y + bf.y;
        v[q].z = v[q].z * rs * wf.z + bf.z;
        v[q].w = v[q].w * rs * wf.w + bf.w;
    }
}

template <int TWO>
__global__ void __launch_bounds__(256)
ln_kernel(const float* __restrict__ in,
          hf* __restrict__ oh, hf* __restrict__ ol,
          const float* __restrict__ w1v, const float* __restrict__ b1,
          const float* __restrict__ w2, const float* __restrict__ b2)
{
    int row = blockIdx.x * 8 + (threadIdx.x >> 5);
    int l = threadIdx.x & 31;
    const float4* xr = (const float4*)(in + (size_t)row * 512);
    float4 v[4];
#pragma unroll
    for (int q = 0; q < 4; q++) v[q] = xr[l + q * 32];
    ln_stage(v, w1v, b1, l);
    if (TWO) ln_stage(v, w2, b2, l);
#pragma unroll
    for (int q = 0; q < 4; q++) {
        size_t off = (size_t)row * 512 + (size_t)(l + q * 32) * 4;
        split4(v[q], oh + off, ol + off);
    }
}

// ---------------- per-layer prep ----------------
__device__ __forceinline__ float2 coef_of(float lr, float li, float lstep,
                                          float* lbx, float* lby)
{
    float st = expf(lstep);
    float er = expf(lr * st);
    float cc = er * cosf(li * st);
    float ss = er * sinf(li * st);
    *lbx = cc; *lby = ss;
    float den = lr * lr + li * li;
    return make_float2(((cc - 1.f) * lr + ss * li) / den, (ss * lr - (cc - 1.f) * li) / den);
}

__device__ __forceinline__ void prep_layer_body(int blk, int tid,
                           const float* __restrict__ lam_re, const float* __restrict__ lam_im,
                           const float* __restrict__ log_step,
                           const float* __restrict__ Bre, const float* __restrict__ Bim,
                           const float* __restrict__ Cre, const float* __restrict__ Cim,
                           const float* __restrict__ ffe, const float* __restrict__ ffd)
{
    if (blk < 1024) {
        int idx = blk * 256 + tid;
        int p = idx >> 9, d = idx & 511;
        float lbx, lby;
        float2 cf = coef_of(lam_re[p], lam_im[p], log_step[p], &lbx, &lby);
        float br = Bre[idx], bi = Bim[idx];
        w1(cf.x * br - cf.y * bi, &g_wbh[(size_t)(2 * p) * 512 + d]);
        w1(cf.x * bi + cf.y * br, &g_wbh[(size_t)(2 * p + 1) * 512 + d]);
    } else if (blk < 2048) {
        int idx = (blk - 1024) * 256 + tid;
        int d = idx >> 9, p = idx & 511;
        w1(2.f * Cre[idx], &g_wch[(size_t)d * 1024 + 2 * p]);
        w1(-2.f * Cim[idx], &g_wch[(size_t)d * 1024 + 2 * p + 1]);
    } else if (blk < 4096) {
        int idx = (blk - 2048) * 256 + tid;
        int r = idx >> 9, k = idx & 511;
        int src = (r & 1) ? (512 + (r >> 1)) : (r >> 1);
        w1(ffe[(size_t)src * 512 + k], &g_feh[(size_t)r * 512 + k]);
    } else if (blk < 5120) {
        int idx = (blk - 4096) * 256 + tid;
        w1(ffd[idx], &g_fdh[idx]);
    } else {
        int p = (blk - 5120) * 256 + tid;
        float lbx, lby;
        coef_of(lam_re[p], lam_im[p], log_step[p], &lbx, &lby);
        g_lb[p] = make_float2(lbx, lby);
        float ar = lbx, ai = lby;
#pragma unroll
        for (int i = 0; i < 7; i++) {
            float nr = ar * ar - ai * ai, ni = 2.f * ar * ai;
            ar = nr; ai = ni;
        }
        g_lbN[p] = make_float2(ar, ai);
    }
}

__global__ void prep_layer(const float* __restrict__ lam_re, const float* __restrict__ lam_im,
                           const float* __restrict__ log_step,
                           const float* __restrict__ Bre, const float* __restrict__ Bim,
                           const float* __restrict__ Cre, const float* __restrict__ Cim,
                           const float* __restrict__ ffe, const float* __restrict__ ffd)
{
    prep_layer_body(blockIdx.x, threadIdx.x, lam_re, lam_im, log_step,
                    Bre, Bim, Cre, Cim, ffe, ffd);
}

__global__ void prep_all(const float* __restrict__ x, const float* __restrict__ enc_w,
                         const float* __restrict__ lam_re, const float* __restrict__ lam_im,
                         const float* __restrict__ log_step,
                         const float* __restrict__ Bre, const float* __restrict__ Bim,
                         const float* __restrict__ Cre, const float* __restrict__ Cim,
                         const float* __restrict__ ffe, const float* __restrict__ ffd)
{
    int blk = blockIdx.x, tid = threadIdx.x;
    if (blk < 2048) {
        int idx = blk * 256 + tid;
        int mrow = idx >> 4, q = idx & 15;
        float4 v = *(const float4*)(x + (size_t)mrow * 64 + q * 4);
        size_t off = (size_t)mrow * 64 + (size_t)q * 4;
        split4(v, g_xbh + off, g_xbl + off);
    } else if (blk < 2176) {
        int idx = (blk - 2048) * 256 + tid;
        int k = idx >> 9, n = idx & 511;
        w1(enc_w[idx], &g_weh[(size_t)n * 64 + k]);
    } else {
        prep_layer_body(blk - 2176, tid, lam_re, lam_im, log_step,
                        Bre, Bim, Cre, Cim, ffe, ffd);
    }
}

// ---------------- scan pass3 (carry combine folded in) ----------------
__global__ void scan_pass3()
{
    const int p = threadIdx.x;
    const int c = blockIdx.x, b = blockIdx.y;
    float2 lb = g_lb[p];
    float2 A = g_lbN[p];
    float2 cv = make_float2(0.f, 0.f);
    for (int k = 0; k < c; k++) {
        float2 ck = g_carry[((size_t)b * NCHK + k) * 512 + p];
        float nr = fmaf(A.x, cv.x, fmaf(-A.y, cv.y, ck.x));
        float ni = fmaf(A.x, cv.y, fmaf(A.y, cv.x, ck.y));
        cv = make_float2(nr, ni);
    }
    float pr = lb.x, pi = lb.y;
    size_t row0 = (size_t)(b * LSEQ + c * CLEN);
    const float2* loc = (const float2*)(g_big + row0 * 1024) + p;
    uint32_t* xh = (uint32_t*)(g_xh + row0 * 1024) + p;
    uint32_t* xl = (uint32_t*)(g_xl + row0 * 1024) + p;
    for (int t = 0; t < CLEN; t++) {
        float2 l = loc[(size_t)t * 512];
        float xr = fmaf(pr, cv.x, fmaf(-pi, cv.y, l.x));
        float xi = fmaf(pr, cv.y, fmaf(pi, cv.x, l.y));
        float nr = pr * lb.x - pi * lb.y;
        pi = pr * lb.y + pi * lb.x; pr = nr;
        hf hr = __float2half_rn(xr);
        hf hi2 = __float2half_rn(xi);
        xh[(size_t)t * 512] = pack2(hr, hi2);
        xl[(size_t)t * 512] = pack2(__float2half_rn(xr - __half2float(hr)),
                                    __float2half_rn(xi - __half2float(hi2)));
    }
}

// ---------------- pool (2-stage) + head ----------------
__global__ void pool_partial(const int* __restrict__ lengths)
{
    const int b = blockIdx.x, c = blockIdx.y;
    const int d = threadIdx.x;
    int len = lengths[b];
    int t0 = c * CLEN;
    int t1 = t0 + CLEN < len ? t0 + CLEN : len;
    float s = 0.f;
    const float* hp = g_h + ((size_t)(b * LSEQ + t0)) * 512 + d;
    for (int t = t0; t < t1; t++) { s += hp[0]; hp += 512; }
    g_pool[((size_t)b * NCHK + c) * 512 + d] = s;
}

__global__ void pool_head(const int* __restrict__ lengths,
                          const float* __restrict__ hw, const float* __restrict__ hb,
                          float* __restrict__ out)
{
    const int b = blockIdx.x;
    const int d = threadIdx.x;
    float s = 0.f;
#pragma unroll
    for (int c = 0; c < NCHK; c++) s += g_pool[((size_t)b * NCHK + c) * 512 + d];
    int len = lengths[b];
    int den = len > 1 ? len : 1;
    float v = (s / (float)den) * hw[d];
    __shared__ float red[512];
    red[d] = v; __syncthreads();
    for (int st = 256; st > 0; st >>= 1) { if (d < st) red[d] += red[d + st]; __syncthreads(); }
    if (d == 0) out[b] = red[0] + hb[0];
}

// ---------------- launch ----------------
extern "C" void kernel_launch(void* const* d_in, const int* in_sizes, int n_in,
                              void* d_out, int out_size)
{
    const float* x       = (const float*)d_in[0];
    const int*   lengths = (const int*)  d_in[1];
    const float* enc_w   = (const float*)d_in[2];
    const float* enc_b   = (const float*)d_in[3];
    const float* lam_re  = (const float*)d_in[4];
    const float* lam_im  = (const float*)d_in[5];
    const float* Bre     = (const float*)d_in[6];
    const float* Bim     = (const float*)d_in[7];
    const float* Cre     = (const float*)d_in[8];
    const float* Cim     = (const float*)d_in[9];
    const float* Dp      = (const float*)d_in[10];
    const float* log_step= (const float*)d_in[11];
    const float* an_w    = (const float*)d_in[12];
    const float* an_b    = (const float*)d_in[13];
    const float* fn_w    = (const float*)d_in[14];
    const float* fn_b    = (const float*)d_in[15];
    const float* ffe_w   = (const float*)d_in[16];
    const float* ffd_w   = (const float*)d_in[17];
    const float* norm_w  = (const float*)d_in[18];
    const float* norm_b  = (const float*)d_in[19];
    const float* head_w  = (const float*)d_in[20];
    const float* head_b  = (const float*)d_in[21];
    float* out = (float*)d_out;

    cudaFuncSetAttribute(gemm_tc<1>, cudaFuncAttributeMaxDynamicSharedMemorySize, GSMEM);
    cudaFuncSetAttribute(gemm_tc<2>, cudaFuncAttributeMaxDynamicSharedMemorySize, GSMEM);
    cudaFuncSetAttribute(gemm_tc<3>, cudaFuncAttributeMaxDynamicSharedMemorySize, GSMEM);
    cudaFuncSetAttribute(gemm_tc<4>, cudaFuncAttributeMaxDynamicSharedMemorySize, GSMEM);
    cudaFuncSetAttribute(gemm_tc<5>, cudaFuncAttributeMaxDynamicSharedMemorySize, GSMEM);

    void *p_h, *p_b2, *p_big, *p_b1h, *p_b1l, *p_xh, *p_xl, *p_xbh, *p_xbl;
    void *p_wbh, *p_wch, *p_feh, *p_fdh, *p_weh;
    cudaGetSymbolAddress(&p_h, g_h);
    cudaGetSymbolAddress(&p_b2, g_b2);   cudaGetSymbolAddress(&p_big, g_big);
    cudaGetSymbolAddress(&p_b1h, g_b1h); cudaGetSymbolAddress(&p_b1l, g_b1l);
    cudaGetSymbolAddress(&p_xh, g_xh);   cudaGetSymbolAddress(&p_xl, g_xl);
    cudaGetSymbolAddress(&p_xbh, g_xbh); cudaGetSymbolAddress(&p_xbl, g_xbl);
    cudaGetSymbolAddress(&p_wbh, g_wbh); cudaGetSymbolAddress(&p_wch, g_wch);
    cudaGetSymbolAddress(&p_feh, g_feh); cudaGetSymbolAddress(&p_fdh, g_fdh);
    cudaGetSymbolAddress(&p_weh, g_weh);
    float* h   = (float*)p_h;
    float* b2  = (float*)p_b2; float* big = (float*)p_big;
    hf* b1h = (hf*)p_b1h; hf* b1l = (hf*)p_b1l;
    hf* xh  = (hf*)p_xh;  hf* xl  = (hf*)p_xl;
    hf* xbh = (hf*)p_xbh; hf* xbl = (hf*)p_xbl;
    hf* wbh = (hf*)p_wbh; hf* wch = (hf*)p_wch;
    hf* feh = (hf*)p_feh; hf* fdh = (hf*)p_fdh;
    hf* weh = (hf*)p_weh;

    prep_all<<<7298, 256>>>(x, enc_w, lam_re, lam_im, log_step,
                            Bre, Bim, Cre, Cim, ffe_w, ffd_w);
    gemm_tc<1><<<dim3(4, 256), 256, GSMEM>>>(xbh, xbl, 64, weh, 64,
                                             h, 512, enc_b, nullptr, nullptr, nullptr, nullptr);

    for (int i = 0; i < NLAYER; i++) {
        if (i > 0)
            prep_layer<<<5122, 256>>>(lam_re + i * 512, lam_im + i * 512, log_step + i * 512,
                                      Bre + (size_t)i * 512 * 512, Bim + (size_t)i * 512 * 512,
                                      Cre + (size_t)i * 512 * 512, Cim + (size_t)i * 512 * 512,
                                      ffe_w + (size_t)i * 1024 * 512, ffd_w + (size_t)i * 512 * 512);
        ln_kernel<1><<<MR / 8, 256>>>(h, b1h, b1l,
                                      norm_w + i * 512, norm_b + i * 512,
                                      an_w + i * 512, an_b + i * 512);
        // launch #4 (i=0): Bu GEMM + fused parallel chunk scan  <- ncu capture target
        gemm_tc<5><<<dim3(8, 256), 256, GSMEM>>>(b1h, b1l, 512, wbh, 512,
                                                 big, 1024, nullptr, nullptr, nullptr, nullptr, nullptr);
        scan_pass3<<<dim3(NCHK, NBATCH), 512>>>();
        gemm_tc<2><<<dim3(4, 256), 256, GSMEM>>>(xh, xl, 1024, wch, 1024,
                                                 b2, 512, Dp + i * 512, b1h, b1l, nullptr, nullptr);
        ln_kernel<0><<<MR / 8, 256>>>(b2, b1h, b1l, fn_w + i * 512, fn_b + i * 512,
                                      nullptr, nullptr);
        gemm_tc<4><<<dim3(8, 256), 256, GSMEM>>>(b1h, b1l, 512, feh, 512,
                                                 nullptr, 512, nullptr, nullptr, nullptr, xh, xl);
        gemm_tc<3><<<dim3(4, 256), 256, GSMEM>>>(xh, xl, 512, fdh, 512,
                                                 h, 512, nullptr, b1h, b1l, nullptr, nullptr);
    }

    pool_partial<<<dim3(NBATCH, NCHK), 512>>>(lengths);
    pool_head<<<NBATCH, 512>>>(lengths, head_w, head_b, out);
}

// round 16
// speedup vs baseline: 1.8878x; 1.2974x over previous
#include <cuda_runtime.h>
#include <cuda_fp16.h>
#include <math.h>
#include <stdint.h>

#define MR 32768
#define LSEQ 4096
#define NBATCH 8
#define NLAYER 3
#define NCHK 32
#define CLEN 128

typedef __half hf;

// ---------------- scratch ----------------
__device__ __align__(256) float g_h  [(size_t)MR * 512];
__device__ __align__(256) float g_b2 [(size_t)MR * 512];
__device__ __align__(256) float g_big[(size_t)MR * 1024];
__device__ __align__(256) hf g_b1h[(size_t)MR * 512];
__device__ __align__(256) hf g_b1l[(size_t)MR * 512];
__device__ __align__(256) hf g_xh [(size_t)MR * 1024];
__device__ __align__(256) hf g_xl [(size_t)MR * 1024];
__device__ __align__(256) hf g_xbh[(size_t)MR * 64];
__device__ __align__(256) hf g_wbh[1024 * 512];
__device__ __align__(256) hf g_wch[512 * 1024];
__device__ __align__(256) hf g_feh[1024 * 512];
__device__ __align__(256) hf g_fdh[512 * 512];
__device__ __align__(256) hf g_weh[512 * 64];
__device__ __align__(256) float2 g_lb[512];
__device__ __align__(256) float2 g_lbN[512];
__device__ __align__(256) float2 g_carry[NBATCH * NCHK * 512];
__device__ __align__(256) float g_pool[NBATCH * NCHK * 512];

__device__ __forceinline__ float geluf(float x) {
    return 0.5f * x * (1.0f + erff(x * 0.70710678118654752f));
}
__device__ __forceinline__ uint32_t s2u(const void* p) {
    uint32_t a;
    asm("{ .reg .u64 t; cvta.to.shared.u64 t, %1; cvt.u32.u64 %0, t; }" : "=r"(a) : "l"(p));
    return a;
}
__device__ __forceinline__ void split1(float v, hf* oh, hf* ol) {
    hf h = __float2half_rn(v);
    *oh = h;
    *ol = __float2half_rn(v - __half2float(h));
}
__device__ __forceinline__ void w1(float v, hf* oh) {
    *oh = __float2half_rn(v);
}
__device__ __forceinline__ uint32_t pack2(hf a, hf b) {
    union { hf h[2]; uint32_t u; } u;
    u.h[0] = a; u.h[1] = b;
    return u.u;
}
__device__ __forceinline__ void split4(float4 y, hf* oh, hf* ol) {
    union { hf b[4]; uint2 u; } H, L;
    float f[4] = {y.x, y.y, y.z, y.w};
#pragma unroll
    for (int e = 0; e < 4; e++) {
        hf h = __float2half_rn(f[e]);
        H.b[e] = h;
        L.b[e] = __float2half_rn(f[e] - __half2float(h));
    }
    *(uint2*)oh = H.u;
    *(uint2*)ol = L.u;
}
__device__ __forceinline__ float2 rec2(const hf* ph, const hf* pl) {
    __half2 hh = *(const __half2*)ph;
    __half2 ll = *(const __half2*)pl;
    return make_float2(__half2float(hh.x) + __half2float(ll.x),
                       __half2float(hh.y) + __half2float(ll.y));
}
__device__ __forceinline__ float2 cmul(float2 a, float2 b) {
    return make_float2(a.x * b.x - a.y * b.y, a.x * b.y + a.y * b.x);
}

#define LDSM4(r0, r1, r2, r3, a) \
    asm volatile("ldmatrix.sync.aligned.m8n8.x4.shared.b16 {%0,%1,%2,%3}, [%4];" \
                 : "=r"(r0), "=r"(r1), "=r"(r2), "=r"(r3) : "r"(a))

#define MMA16816(c, a0, a1, a2, a3, b0, b1) \
    asm volatile("mma.sync.aligned.m16n8k16.row.col.f32.f16.f16.f32 " \
                 "{%0,%1,%2,%3}, {%4,%5,%6,%7}, {%8,%9}, {%0,%1,%2,%3};" \
                 : "+f"((c)[0]), "+f"((c)[1]), "+f"((c)[2]), "+f"((c)[3]) \
                 : "r"(a0), "r"(a1), "r"(a2), "r"(a3), "r"(b0), "r"(b1))

// ---------------- HMMA GEMM: 128x128 block, BK=64, 2-stage swizzled, 2 blocks/SM ---
// TT = number of A terms (1: C = Ah*Wh ; 2: C = (Ah+Al)*Wh)
#define MATB 16384
#define GSMEM (2 * 3 * MATB)
#define SCARRY_OFF 65536

__device__ __forceinline__ uint32_t swadr(uint32_t row, uint32_t c16) {
    return row * 128 + ((c16 ^ (row & 7)) << 4);
}

template <int EPI, int TT>
__global__ void __launch_bounds__(256, 2)
gemm_tc(const hf* __restrict__ Ah, const hf* __restrict__ Al, int lda,
        const hf* __restrict__ Wh, int K,
        float* __restrict__ C, int ldc,
        const float* __restrict__ vec,
        const hf* __restrict__ math, const hf* __restrict__ matl,
        hf* __restrict__ oh)
{
    extern __shared__ char smembuf[];
    const uint32_t sb = s2u(smembuf);
    const int tid = threadIdx.x, lane = tid & 31, wid = tid >> 5;
    const int warpM = wid & 3, warpN = wid >> 2;
    const int bm = blockIdx.y << 7, bn = blockIdx.x << 7;
    const int NCH = K >> 6;
    const int NMAT = (TT == 2) ? 3 : 2;
    const int WOFF = (TT == 2) ? 2 * MATB : MATB;
    const int STG = NMAT * MATB;

    float c[2][8][4];
#pragma unroll
    for (int i = 0; i < 2; i++)
#pragma unroll
        for (int j = 0; j < 8; j++)
#pragma unroll
            for (int q = 0; q < 4; q++) c[i][j][q] = 0.f;

    auto LOAD = [&](int ch) {
        if (ch < NCH) {
            uint32_t base = sb + (ch & 1) * STG;
            const hf* gp[3];
            int ld3[3];
            gp[0] = Ah + (size_t)bm * lda + ch * 64;            ld3[0] = lda;
            if (TT == 2) { gp[1] = Al + (size_t)bm * lda + ch * 64; ld3[1] = lda; }
            gp[NMAT - 1] = Wh + (size_t)bn * K + ch * 64;        ld3[NMAT - 1] = K;
#pragma unroll
            for (int mt = 0; mt < NMAT; mt++) {
                uint32_t mb = base + mt * MATB;
                const hf* g = gp[mt];
                int ld = ld3[mt];
#pragma unroll
                for (int q = 0; q < 4; q++) {
                    int idx = tid + q * 256;
                    uint32_t row = idx >> 3, c16 = idx & 7;
                    uint32_t d = mb + swadr(row, c16);
                    const hf* src = g + (size_t)row * ld + c16 * 8;
                    asm volatile("cp.async.cg.shared.global [%0], [%1], 16;"
                                 :: "r"(d), "l"(src) : "memory");
                }
            }
        }
        asm volatile("cp.async.commit_group;" ::: "memory");
    };

    LOAD(0);

    for (int ch = 0; ch < NCH; ch++) {
        asm volatile("cp.async.wait_group 0;" ::: "memory");
        __syncthreads();
        LOAD(ch + 1);

        uint32_t base = sb + (ch & 1) * STG;
#pragma unroll
        for (int kk = 0; kk < 4; kk++) {
            uint32_t c16 = kk * 2 + (lane >> 4);
            uint32_t ah[2][4], al[2][4];
#pragma unroll
            for (int mf = 0; mf < 2; mf++) {
                uint32_t row = warpM * 32 + mf * 16 + (lane & 15);
                uint32_t a0 = base + swadr(row, c16);
                LDSM4(ah[mf][0], ah[mf][1], ah[mf][2], ah[mf][3], a0);
                if (TT == 2)
                    LDSM4(al[mf][0], al[mf][1], al[mf][2], al[mf][3], a0 + MATB);
            }
#pragma unroll
            for (int g = 0; g < 4; g++) {
                uint32_t row = warpN * 64 + g * 16 + (lane & 15);
                uint32_t a0 = base + WOFF + swadr(row, c16);
                uint32_t h0, h1, h2, h3;
                LDSM4(h0, h1, h2, h3, a0);
#pragma unroll
                for (int mf = 0; mf < 2; mf++) {
                    MMA16816(c[mf][2*g],   ah[mf][0], ah[mf][1], ah[mf][2], ah[mf][3], h0, h2);
                    MMA16816(c[mf][2*g+1], ah[mf][0], ah[mf][1], ah[mf][2], ah[mf][3], h1, h3);
                }
                if (TT == 2) {
#pragma unroll
                    for (int mf = 0; mf < 2; mf++) {
                        MMA16816(c[mf][2*g],   al[mf][0], al[mf][1], al[mf][2], al[mf][3], h0, h2);
                        MMA16816(c[mf][2*g+1], al[mf][0], al[mf][1], al[mf][2], al[mf][3], h1, h3);
                    }
                }
            }
        }
    }

    if (EPI == 5) {
        // parallel segmented scan: 64 complex chains x 4 segments of 32 steps
        float* sc = (float*)smembuf;
        float2* scar = (float2*)(smembuf + SCARRY_OFF);
        __syncthreads();
#pragma unroll
        for (int mf = 0; mf < 2; mf++) {
            int r0 = warpM * 32 + mf * 16 + (lane >> 2);
#pragma unroll
            for (int jb = 0; jb < 8; jb++) {
                int n = warpN * 64 + jb * 8 + 2 * (lane & 3);
#pragma unroll
                for (int half = 0; half < 2; half++) {
                    *(float2*)&sc[(r0 + half * 8) * 128 + n] =
                        make_float2(c[mf][jb][2 * half], c[mf][jb][2 * half + 1]);
                }
            }
        }
        __syncthreads();
        {
            int j = tid & 63, seg = tid >> 6;
            int t0 = seg * 32;
            int pglob = (bn >> 1) + j;
            float2 lb = g_lb[pglob];
            float xr = 0.f, xi = 0.f;
#pragma unroll 4
            for (int t = 0; t < 32; t++) {
                float2* pp = (float2*)&sc[(t0 + t) * 128 + 2 * j];
                float2 bu = *pp;
                float nr = fmaf(lb.x, xr, fmaf(-lb.y, xi, bu.x));
                float ni = fmaf(lb.x, xi, fmaf(lb.y, xr, bu.y));
                xr = nr; xi = ni;
                *pp = make_float2(xr, xi);
            }
            scar[seg * 64 + j] = make_float2(xr, xi);
            __syncthreads();
            float2 pw32 = lb;
#pragma unroll
            for (int q = 0; q < 5; q++) pw32 = cmul(pw32, pw32);
            float2 s = make_float2(0.f, 0.f);
            for (int k = 0; k < seg; k++) {
                float2 ck = scar[k * 64 + j];
                float nr = fmaf(pw32.x, s.x, fmaf(-pw32.y, s.y, ck.x));
                float ni = fmaf(pw32.x, s.y, fmaf(pw32.y, s.x, ck.y));
                s = make_float2(nr, ni);
            }
            float* outp = g_big + (size_t)(bm + t0) * 1024 + bn + 2 * j;
            float2 pw = lb;
            float2 last = make_float2(0.f, 0.f);
#pragma unroll 4
            for (int t = 0; t < 32; t++) {
                float2 l = *(float2*)&sc[(t0 + t) * 128 + 2 * j];
                float2 v = make_float2(fmaf(pw.x, s.x, fmaf(-pw.y, s.y, l.x)),
                                       fmaf(pw.x, s.y, fmaf(pw.y, s.x, l.y)));
                *(float2*)(outp + (size_t)t * 1024) = v;
                pw = cmul(pw, lb);
                last = v;
            }
            if (seg == 3) {
                int b = bm >> 12, cch = (bm >> 7) & 31;
                g_carry[((size_t)b * NCHK + cch) * 512 + pglob] = last;
            }
        }
        return;
    }

#pragma unroll
    for (int mf = 0; mf < 2; mf++) {
        int m0 = bm + warpM * 32 + mf * 16 + (lane >> 2);
#pragma unroll
        for (int jb = 0; jb < 8; jb++) {
            int n = bn + warpN * 64 + jb * 8 + 2 * (lane & 3);
#pragma unroll
            for (int half = 0; half < 2; half++) {
                int r = m0 + half * 8;
                float v0 = c[mf][jb][2 * half], v1 = c[mf][jb][2 * half + 1];
                if (EPI == 4) {
                    int j = ((bn + warpN * 64 + jb * 8) >> 1) + (lane & 3);
                    w1(v0 * geluf(v1), oh + (size_t)r * 512 + j);
                } else {
                    size_t off = (size_t)r * ldc + n;
                    if (EPI == 1) {
                        float2 bv = *(const float2*)(vec + n);
                        v0 += bv.x; v1 += bv.y;
                    } else if (EPI == 2) {
                        float2 u = rec2(math + (size_t)r * 512 + n, matl + (size_t)r * 512 + n);
                        float2 dv = *(const float2*)(vec + n);
                        v0 = geluf(v0 + dv.x * u.x) + u.x;
                        v1 = geluf(v1 + dv.y * u.y) + u.y;
                    } else if (EPI == 3) {
                        float2 u = rec2(math + (size_t)r * 512 + n, matl + (size_t)r * 512 + n);
                        float2 co = *(const float2*)(C + off);
                        v0 += co.x + u.x; v1 += co.y + u.y;
                    }
                    *(float2*)(C + off) = make_float2(v0, v1);
                }
            }
        }
    }
}

// ---------------- LayerNorm (warp per row) ----------------
__device__ __forceinline__ float wsum(float x) {
#pragma unroll
    for (int o = 16; o; o >>= 1) x += __shfl_xor_sync(0xFFFFFFFFu, x, o);
    return x;
}
__device__ __forceinline__ void ln_stage(float4 v[4], const float* __restrict__ w,
                                         const float* __restrict__ b, int l) {
    float s = 0.f;
#pragma unroll
    for (int q = 0; q < 4; q++) s += v[q].x + v[q].y + v[q].z + v[q].w;
    float mean = wsum(s) * (1.f / 512.f);
    float vv = 0.f;
#pragma unroll
    for (int q = 0; q < 4; q++) {
        v[q].x -= mean; v[q].y -= mean; v[q].z -= mean; v[q].w -= mean;
        vv += v[q].x * v[q].x + v[q].y * v[q].y + v[q].z * v[q].z + v[q].w * v[q].w;
    }
    float rs = rsqrtf(wsum(vv) * (1.f / 512.f) + 1e-5f);
#pragma unroll
    for (int q = 0; q < 4; q++) {
        int cc = (l + q * 32) * 4;
        float4 wf = *(const float4*)(w + cc);
        float4 bf = *(const float4*)(b + cc);
        v[q].x = v[q].x * rs * wf.x + bf.x;
        v[q].y = v[q].y * rs * wf.y + bf.y;
        v[q].z = v[q].z * rs * wf.z + bf.z;
        v[q].w = v[q].w * rs * wf.w + bf.w;
    }
}

template <int TWO>
__global__ void __launch_bounds__(256)
ln_kernel(const float* __restrict__ in,
          hf* __restrict__ oh, hf* __restrict__ ol,
          const float* __restrict__ w1v, const float* __restrict__ b1,
          const float* __restrict__ w2, const float* __restrict__ b2)
{
    int row = blockIdx.x * 8 + (threadIdx.x >> 5);
    int l = threadIdx.x & 31;
    const float4* xr = (const float4*)(in + (size_t)row * 512);
    float4 v[4];
#pragma unroll
    for (int q = 0; q < 4; q++) v[q] = xr[l + q * 32];
    ln_stage(v, w1v, b1, l);
    if (TWO) ln_stage(v, w2, b2, l);
#pragma unroll
    for (int q = 0; q < 4; q++) {
        size_t off = (size_t)row * 512 + (size_t)(l + q * 32) * 4;
        split4(v[q], oh + off, ol + off);
    }
}

// ---------------- per-layer prep ----------------
__device__ __forceinline__ float2 coef_of(float lr, float li, float lstep,
                                          float* lbx, float* lby)
{
    float st = expf(lstep);
    float er = expf(lr * st);
    float cc = er * cosf(li * st);
    float ss = er * sinf(li * st);
    *lbx = cc; *lby = ss;
    float den = lr * lr + li * li;
    return make_float2(((cc - 1.f) * lr + ss * li) / den, (ss * lr - (cc - 1.f) * li) / den);
}

__device__ __forceinline__ void prep_layer_body(int blk, int tid,
                           const float* __restrict__ lam_re, const float* __restrict__ lam_im,
                           const float* __restrict__ log_step,
                           const float* __restrict__ Bre, const float* __restrict__ Bim,
                           const float* __restrict__ Cre, const float* __restrict__ Cim,
                           const float* __restrict__ ffe, const float* __restrict__ ffd)
{
    if (blk < 1024) {
        int idx = blk * 256 + tid;
        int p = idx >> 9, d = idx & 511;
        float lbx, lby;
        float2 cf = coef_of(lam_re[p], lam_im[p], log_step[p], &lbx, &lby);
        float br = Bre[idx], bi = Bim[idx];
        w1(cf.x * br - cf.y * bi, &g_wbh[(size_t)(2 * p) * 512 + d]);
        w1(cf.x * bi + cf.y * br, &g_wbh[(size_t)(2 * p + 1) * 512 + d]);
    } else if (blk < 2048) {
        int idx = (blk - 1024) * 256 + tid;
        int d = idx >> 9, p = idx & 511;
        w1(2.f * Cre[idx], &g_wch[(size_t)d * 1024 + 2 * p]);
        w1(-2.f * Cim[idx], &g_wch[(size_t)d * 1024 + 2 * p + 1]);
    } else if (blk < 4096) {
        int idx = (blk - 2048) * 256 + tid;
        int r = idx >> 9, k = idx & 511;
        int src = (r & 1) ? (512 + (r >> 1)) : (r >> 1);
        w1(ffe[(size_t)src * 512 + k], &g_feh[(size_t)r * 512 + k]);
    } else if (blk < 5120) {
        int idx = (blk - 4096) * 256 + tid;
        w1(ffd[idx], &g_fdh[idx]);
    } else {
        int p = (blk - 5120) * 256 + tid;
        float lbx, lby;
        coef_of(lam_re[p], lam_im[p], log_step[p], &lbx, &lby);
        g_lb[p] = make_float2(lbx, lby);
        float ar = lbx, ai = lby;
#pragma unroll
        for (int i = 0; i < 7; i++) {
            float nr = ar * ar - ai * ai, ni = 2.f * ar * ai;
            ar = nr; ai = ni;
        }
        g_lbN[p] = make_float2(ar, ai);
    }
}

__global__ void prep_layer(const float* __restrict__ lam_re, const float* __restrict__ lam_im,
                           const float* __restrict__ log_step,
                           const float* __restrict__ Bre, const float* __restrict__ Bim,
                           const float* __restrict__ Cre, const float* __restrict__ Cim,
                           const float* __restrict__ ffe, const float* __restrict__ ffd)
{
    prep_layer_body(blockIdx.x, threadIdx.x, lam_re, lam_im, log_step,
                    Bre, Bim, Cre, Cim, ffe, ffd);
}

__global__ void prep_all(const float* __restrict__ x, const float* __restrict__ enc_w,
                         const float* __restrict__ lam_re, const float* __restrict__ lam_im,
                         const float* __restrict__ log_step,
                         const float* __restrict__ Bre, const float* __restrict__ Bim,
                         const float* __restrict__ Cre, const float* __restrict__ Cim,
                         const float* __restrict__ ffe, const float* __restrict__ ffd)
{
    int blk = blockIdx.x, tid = threadIdx.x;
    if (blk < 2048) {
        int idx = blk * 256 + tid;
        int mrow = idx >> 4, q = idx & 15;
        float4 v = *(const float4*)(x + (size_t)mrow * 64 + q * 4);
        size_t off = (size_t)mrow * 64 + (size_t)q * 4;
        union { hf b[4]; uint2 u; } H;
        H.b[0] = __float2half_rn(v.x); H.b[1] = __float2half_rn(v.y);
        H.b[2] = __float2half_rn(v.z); H.b[3] = __float2half_rn(v.w);
        *(uint2*)(g_xbh + off) = H.u;
    } else if (blk < 2176) {
        int idx = (blk - 2048) * 256 + tid;
        int k = idx >> 9, n = idx & 511;
        w1(enc_w[idx], &g_weh[(size_t)n * 64 + k]);
    } else {
        prep_layer_body(blk - 2176, tid, lam_re, lam_im, log_step,
                        Bre, Bim, Cre, Cim, ffe, ffd);
    }
}

// ---------------- scan pass3 (carry combine folded in) ----------------
__global__ void scan_pass3()
{
    const int p = threadIdx.x;
    const int c = blockIdx.x, b = blockIdx.y;
    float2 lb = g_lb[p];
    float2 A = g_lbN[p];
    float2 cv = make_float2(0.f, 0.f);
    for (int k = 0; k < c; k++) {
        float2 ck = g_carry[((size_t)b * NCHK + k) * 512 + p];
        float nr = fmaf(A.x, cv.x, fmaf(-A.y, cv.y, ck.x));
        float ni = fmaf(A.x, cv.y, fmaf(A.y, cv.x, ck.y));
        cv = make_float2(nr, ni);
    }
    float pr = lb.x, pi = lb.y;
    size_t row0 = (size_t)(b * LSEQ + c * CLEN);
    const float2* loc = (const float2*)(g_big + row0 * 1024) + p;
    uint32_t* xh = (uint32_t*)(g_xh + row0 * 1024) + p;
    uint32_t* xl = (uint32_t*)(g_xl + row0 * 1024) + p;
    for (int t = 0; t < CLEN; t++) {
        float2 l = loc[(size_t)t * 512];
        float xr = fmaf(pr, cv.x, fmaf(-pi, cv.y, l.x));
        float xi = fmaf(pr, cv.y, fmaf(pi, cv.x, l.y));
        float nr = pr * lb.x - pi * lb.y;
        pi = pr * lb.y + pi * lb.x; pr = nr;
        hf hr = __float2half_rn(xr);
        hf hi2 = __float2half_rn(xi);
        xh[(size_t)t * 512] = pack2(hr, hi2);
        xl[(size_t)t * 512] = pack2(__float2half_rn(xr - __half2float(hr)),
                                    __float2half_rn(xi - __half2float(hi2)));
    }
}

// ---------------- pool (2-stage) + head ----------------
__global__ void pool_partial(const int* __restrict__ lengths)
{
    const int b = blockIdx.x, c = blockIdx.y;
    const int d = threadIdx.x;
    int len = lengths[b];
    int t0 = c * CLEN;
    int t1 = t0 + CLEN < len ? t0 + CLEN : len;
    float s = 0.f;
    const float* hp = g_h + ((size_t)(b * LSEQ + t0)) * 512 + d;
    for (int t = t0; t < t1; t++) { s += hp[0]; hp += 512; }
    g_pool[((size_t)b * NCHK + c) * 512 + d] = s;
}

__global__ void pool_head(const int* __restrict__ lengths,
                          const float* __restrict__ hw, const float* __restrict__ hb,
                          float* __restrict__ out)
{
    const int b = blockIdx.x;
    const int d = threadIdx.x;
    float s = 0.f;
#pragma unroll
    for (int c = 0; c < NCHK; c++) s += g_pool[((size_t)b * NCHK + c) * 512 + d];
    int len = lengths[b];
    int den = len > 1 ? len : 1;
    float v = (s / (float)den) * hw[d];
    __shared__ float red[512];
    red[d] = v; __syncthreads();
    for (int st = 256; st > 0; st >>= 1) { if (d < st) red[d] += red[d + st]; __syncthreads(); }
    if (d == 0) out[b] = red[0] + hb[0];
}

// ---------------- launch ----------------
extern "C" void kernel_launch(void* const* d_in, const int* in_sizes, int n_in,
                              void* d_out, int out_size)
{
    const float* x       = (const float*)d_in[0];
    const int*   lengths = (const int*)  d_in[1];
    const float* enc_w   = (const float*)d_in[2];
    const float* enc_b   = (const float*)d_in[3];
    const float* lam_re  = (const float*)d_in[4];
    const float* lam_im  = (const float*)d_in[5];
    const float* Bre     = (const float*)d_in[6];
    const float* Bim     = (const float*)d_in[7];
    const float* Cre     = (const float*)d_in[8];
    const float* Cim     = (const float*)d_in[9];
    const float* Dp      = (const float*)d_in[10];
    const float* log_step= (const float*)d_in[11];
    const float* an_w    = (const float*)d_in[12];
    const float* an_b    = (const float*)d_in[13];
    const float* fn_w    = (const float*)d_in[14];
    const float* fn_b    = (const float*)d_in[15];
    const float* ffe_w   = (const float*)d_in[16];
    const float* ffd_w   = (const float*)d_in[17];
    const float* norm_w  = (const float*)d_in[18];
    const float* norm_b  = (const float*)d_in[19];
    const float* head_w  = (const float*)d_in[20];
    const float* head_b  = (const float*)d_in[21];
    float* out = (float*)d_out;

    cudaFuncSetAttribute(gemm_tc<1,1>, cudaFuncAttributeMaxDynamicSharedMemorySize, GSMEM);
    cudaFuncSetAttribute(gemm_tc<2,2>, cudaFuncAttributeMaxDynamicSharedMemorySize, GSMEM);
    cudaFuncSetAttribute(gemm_tc<3,1>, cudaFuncAttributeMaxDynamicSharedMemorySize, GSMEM);
    cudaFuncSetAttribute(gemm_tc<4,1>, cudaFuncAttributeMaxDynamicSharedMemorySize, GSMEM);
    cudaFuncSetAttribute(gemm_tc<5,1>, cudaFuncAttributeMaxDynamicSharedMemorySize, GSMEM);

    void *p_h, *p_b2, *p_big, *p_b1h, *p_b1l, *p_xh, *p_xl, *p_xbh;
    void *p_wbh, *p_wch, *p_feh, *p_fdh, *p_weh;
    cudaGetSymbolAddress(&p_h, g_h);
    cudaGetSymbolAddress(&p_b2, g_b2);   cudaGetSymbolAddress(&p_big, g_big);
    cudaGetSymbolAddress(&p_b1h, g_b1h); cudaGetSymbolAddress(&p_b1l, g_b1l);
    cudaGetSymbolAddress(&p_xh, g_xh);   cudaGetSymbolAddress(&p_xl, g_xl);
    cudaGetSymbolAddress(&p_xbh, g_xbh);
    cudaGetSymbolAddress(&p_wbh, g_wbh); cudaGetSymbolAddress(&p_wch, g_wch);
    cudaGetSymbolAddress(&p_feh, g_feh); cudaGetSymbolAddress(&p_fdh, g_fdh);
    cudaGetSymbolAddress(&p_weh, g_weh);
    float* h   = (float*)p_h;
    float* b2  = (float*)p_b2; float* big = (float*)p_big;
    hf* b1h = (hf*)p_b1h; hf* b1l = (hf*)p_b1l;
    hf* xh  = (hf*)p_xh;  hf* xl  = (hf*)p_xl;
    hf* xbh = (hf*)p_xbh;
    hf* wbh = (hf*)p_wbh; hf* wch = (hf*)p_wch;
    hf* feh = (hf*)p_feh; hf* fdh = (hf*)p_fdh;
    hf* weh = (hf*)p_weh;

    prep_all<<<7298, 256>>>(x, enc_w, lam_re, lam_im, log_step,
                            Bre, Bim, Cre, Cim, ffe_w, ffd_w);
    gemm_tc<1,1><<<dim3(4, 256), 256, GSMEM>>>(xbh, nullptr, 64, weh, 64,
                                               h, 512, enc_b, nullptr, nullptr, nullptr);

    for (int i = 0; i < NLAYER; i++) {
        if (i > 0)
            prep_layer<<<5122, 256>>>(lam_re + i * 512, lam_im + i * 512, log_step + i * 512,
                                      Bre + (size_t)i * 512 * 512, Bim + (size_t)i * 512 * 512,
                                      Cre + (size_t)i * 512 * 512, Cim + (size_t)i * 512 * 512,
                                      ffe_w + (size_t)i * 1024 * 512, ffd_w + (size_t)i * 512 * 512);
        ln_kernel<1><<<MR / 8, 256>>>(h, b1h, b1l,
                                      norm_w + i * 512, norm_b + i * 512,
                                      an_w + i * 512, an_b + i * 512);
        // Bu GEMM (1-term) + fused parallel chunk scan  <- ncu capture target (i=0)
        gemm_tc<5,1><<<dim3(8, 256), 256, GSMEM>>>(b1h, nullptr, 512, wbh, 512,
                                                   big, 1024, nullptr, nullptr, nullptr, nullptr);
        scan_pass3<<<dim3(NCHK, NBATCH), 512>>>();
        // C GEMM: 2-term (xs has the widest dynamic range)
        gemm_tc<2,2><<<dim3(4, 256), 256, GSMEM>>>(xh, xl, 1024, wch, 1024,
                                                   b2, 512, Dp + i * 512, b1h, b1l, nullptr);
        ln_kernel<0><<<MR / 8, 256>>>(b2, b1h, b1l, fn_w + i * 512, fn_b + i * 512,
                                      nullptr, nullptr);
        // GEGLU fused (1-term): a*gelu(g) -> xh (hi only)
        gemm_tc<4,1><<<dim3(8, 256), 256, GSMEM>>>(b1h, nullptr, 512, feh, 512,
                                                   nullptr, 512, nullptr, nullptr, nullptr, xh);
        // h += m @ ffd^T + fx2 (1-term)
        gemm_tc<3,1><<<dim3(4, 256), 256, GSMEM>>>(xh, nullptr, 512, fdh, 512,
                                                   h, 512, nullptr, b1h, b1l, nullptr);
    }

    pool_partial<<<dim3(NBATCH, NCHK), 512>>>(lengths);
    pool_head<<<NBATCH, 512>>>(lengths, head_w, head_b, out);
}